// round 1
// baseline (speedup 1.0000x reference)
#include <cuda_runtime.h>
#include <cuda_bf16.h>
#include <math.h>

// ============================================================================
// LogLinearAttention  (B=4, T=4096, C=1024, H=16, dh=64, nc=8, cs=512)
//
// Stage 1: lam[h][t]   = sigmoid( relu(log(t+1)*Wl1 + bl1) @ Wl2.T + bl2 )
// Stage 2: qkv GEMM    [16384,1024] @ [1024,3072]^T -> q,k,v in [B,H,T,64]
//                      (q pre-scaled by dh^-0.5)
// Stage 3: chunked attention with multiplicative key gate lam, per (b,h,chunk)
// Stage 4: out GEMM    [16384,1024] @ [1024,1024]^T + bias -> d_out
// All fp32.
// ============================================================================

#define BATCH 4
#define SEQ   4096
#define CDIM  1024
#define HEADS 16
#define DH    64
#define NCHUNK 8
#define CS    512           // chunk size
#define QT    128           // query tile
#define KT    128           // key tile
#define M_TOT (BATCH * SEQ) // 16384

__device__ float g_q[(size_t)BATCH * HEADS * SEQ * DH];
__device__ float g_k[(size_t)BATCH * HEADS * SEQ * DH];
__device__ float g_v[(size_t)BATCH * HEADS * SEQ * DH];
__device__ float g_attn[(size_t)BATCH * SEQ * CDIM];
__device__ float g_lam[HEADS * SEQ];

// ----------------------------------------------------------------------------
// Stage 1: lambda gates. One thread per position t.
// ----------------------------------------------------------------------------
__global__ void lam_kernel(const float* __restrict__ Wl1, const float* __restrict__ bl1,
                           const float* __restrict__ Wl2, const float* __restrict__ bl2) {
    int t = blockIdx.x * blockDim.x + threadIdx.x;
    if (t >= SEQ) return;
    float lp = logf((float)t + 1.0f);
    float h1[64];
#pragma unroll
    for (int u = 0; u < 64; u++) {
        float v = lp * Wl1[u] + bl1[u];
        h1[u] = v > 0.0f ? v : 0.0f;
    }
#pragma unroll
    for (int h = 0; h < HEADS; h++) {
        float s = bl2[h];
#pragma unroll
        for (int u = 0; u < 64; u++) s += h1[u] * Wl2[h * 64 + u];
        g_lam[h * SEQ + t] = 1.0f / (1.0f + expf(-s));
    }
}

// ----------------------------------------------------------------------------
// Stage 2: qkv GEMM.  C[m,n] = sum_k X[m,k] * W[n,k],  M=16384, N=3072, K=1024
// 128x128x16 tile, 256 threads, 8x8 microtile. Epilogue scatters into
// q/k/v [B,H,T,64] layout; q scaled by 0.125.
// ----------------------------------------------------------------------------
#define BM 128
#define BN 128
#define BK 16

__global__ __launch_bounds__(256) void qkv_gemm(const float* __restrict__ X,
                                                const float* __restrict__ W) {
    __shared__ float As[BK][BM];
    __shared__ float Bs[BK][BN];
    const int tid = threadIdx.x;
    const int ty = tid >> 4, tx = tid & 15;
    const int bm = blockIdx.y * BM;
    const int bn = blockIdx.x * BN;

    float acc[8][8];
#pragma unroll
    for (int i = 0; i < 8; i++)
#pragma unroll
        for (int j = 0; j < 8; j++) acc[i][j] = 0.0f;

    for (int k0 = 0; k0 < CDIM; k0 += BK) {
#pragma unroll
        for (int l = 0; l < 2; l++) {
            int idx = tid + l * 256;      // 0..511 float4s
            int m = idx >> 2;
            int k4 = idx & 3;
            float4 va = *(const float4*)(X + (size_t)(bm + m) * CDIM + k0 + k4 * 4);
            As[k4 * 4 + 0][m] = va.x; As[k4 * 4 + 1][m] = va.y;
            As[k4 * 4 + 2][m] = va.z; As[k4 * 4 + 3][m] = va.w;
            float4 vb = *(const float4*)(W + (size_t)(bn + m) * CDIM + k0 + k4 * 4);
            Bs[k4 * 4 + 0][m] = vb.x; Bs[k4 * 4 + 1][m] = vb.y;
            Bs[k4 * 4 + 2][m] = vb.z; Bs[k4 * 4 + 3][m] = vb.w;
        }
        __syncthreads();
#pragma unroll 4
        for (int kk = 0; kk < BK; kk++) {
            float4 a0 = *(float4*)&As[kk][ty * 8];
            float4 a1 = *(float4*)&As[kk][ty * 8 + 4];
            float4 b0 = *(float4*)&Bs[kk][tx * 8];
            float4 b1 = *(float4*)&Bs[kk][tx * 8 + 4];
            float a[8] = {a0.x, a0.y, a0.z, a0.w, a1.x, a1.y, a1.z, a1.w};
            float b[8] = {b0.x, b0.y, b0.z, b0.w, b1.x, b1.y, b1.z, b1.w};
#pragma unroll
            for (int i = 0; i < 8; i++)
#pragma unroll
                for (int j = 0; j < 8; j++) acc[i][j] += a[i] * b[j];
        }
        __syncthreads();
    }

    // epilogue: scatter into [B,H,T,64] layouts
#pragma unroll
    for (int i = 0; i < 8; i++) {
        int m = bm + ty * 8 + i;
        int bb = m >> 12;
        int t = m & 4095;
#pragma unroll
        for (int jg = 0; jg < 2; jg++) {
            int n0 = bn + tx * 8 + jg * 4;
            int which = n0 >> 10;
            int c = n0 & 1023;
            int h = c >> 6, d = c & 63;
            size_t dst = ((size_t)(bb * HEADS + h) * SEQ + t) * DH + d;
            float4 v = make_float4(acc[i][jg * 4 + 0], acc[i][jg * 4 + 1],
                                   acc[i][jg * 4 + 2], acc[i][jg * 4 + 3]);
            if (which == 0) {
                v.x *= 0.125f; v.y *= 0.125f; v.z *= 0.125f; v.w *= 0.125f;
                *(float4*)(g_q + dst) = v;
            } else if (which == 1) {
                *(float4*)(g_k + dst) = v;
            } else {
                *(float4*)(g_v + dst) = v;
            }
        }
    }
}

// ----------------------------------------------------------------------------
// Stage 3: chunked attention with key gate, flash-style online softmax.
// Block = (b, h, chunk, qtile). 256 threads. 128 queries x 512 keys x 64 dh.
// smem: sQ[64][128] (transposed), sK[64][128] (transposed), sV[128][64],
//       sP[128][128], slam[512]
// ----------------------------------------------------------------------------
#define ATTN_SMEM_FLOATS (64 * 128 + 64 * 128 + 128 * 64 + 128 * 128 + 512)
#define ATTN_SMEM_BYTES (ATTN_SMEM_FLOATS * 4)

__global__ __launch_bounds__(256) void attn_kernel() {
    extern __shared__ float sm[];
    float* sQ = sm;                      // [d][r] 64x128
    float* sK = sQ + 64 * 128;           // [d][r] 64x128
    float* sV = sK + 64 * 128;           // [k][d] 128x64
    float* sP = sV + 128 * 64;           // [r][k] 128x128
    float* slam = sP + 128 * 128;        // [512]

    const int bx = blockIdx.x;
    const int qt = bx & 3;
    const int chunk = (bx >> 2) & 7;
    const int h = (bx >> 5) & 15;
    const int b = bx >> 9;
    const int tid = threadIdx.x;
    const int ty = tid >> 4, tx = tid & 15;

    const size_t head_base = ((size_t)(b * HEADS + h) * SEQ + chunk * CS) * DH;
    const float* Qg = g_q + head_base + (size_t)qt * QT * DH;
    const float* Kg = g_k + head_base;
    const float* Vg = g_v + head_base;

    // load lambda for this chunk
    for (int j = tid; j < CS; j += 256) slam[j] = g_lam[h * SEQ + chunk * CS + j];

    // load Q tile transposed: sQ[d][r]
#pragma unroll
    for (int l = 0; l < 8; l++) {
        int idx = tid + l * 256;         // 0..2047 float4s
        int r = idx >> 4;
        int d4 = idx & 15;
        float4 v = *(const float4*)(Qg + (size_t)r * DH + d4 * 4);
        sQ[(d4 * 4 + 0) * 128 + r] = v.x;
        sQ[(d4 * 4 + 1) * 128 + r] = v.y;
        sQ[(d4 * 4 + 2) * 128 + r] = v.z;
        sQ[(d4 * 4 + 3) * 128 + r] = v.w;
    }

    float O[8][4];
    float mrow[8], lrow[8];
#pragma unroll
    for (int i = 0; i < 8; i++) {
        mrow[i] = -1e30f;
        lrow[i] = 0.0f;
#pragma unroll
        for (int c = 0; c < 4; c++) O[i][c] = 0.0f;
    }

    for (int kt = 0; kt < 4; kt++) {
        __syncthreads();   // previous iteration's sK/sV/sP reads complete (also covers sQ init)
        // load K tile transposed, V tile direct
#pragma unroll
        for (int l = 0; l < 8; l++) {
            int idx = tid + l * 256;
            int r = idx >> 4;
            int d4 = idx & 15;
            float4 vk = *(const float4*)(Kg + ((size_t)kt * KT + r) * DH + d4 * 4);
            sK[(d4 * 4 + 0) * 128 + r] = vk.x;
            sK[(d4 * 4 + 1) * 128 + r] = vk.y;
            sK[(d4 * 4 + 2) * 128 + r] = vk.z;
            sK[(d4 * 4 + 3) * 128 + r] = vk.w;
            float4 vv = *(const float4*)(Vg + ((size_t)kt * KT + r) * DH + d4 * 4);
            *(float4*)(sV + r * 64 + d4 * 4) = vv;
        }
        __syncthreads();

        // S = Q @ K^T  (q pre-scaled)
        float acc[8][8];
#pragma unroll
        for (int i = 0; i < 8; i++)
#pragma unroll
            for (int j = 0; j < 8; j++) acc[i][j] = 0.0f;
#pragma unroll 2
        for (int kk = 0; kk < 64; kk++) {
            float4 a0 = *(float4*)&sQ[kk * 128 + ty * 8];
            float4 a1 = *(float4*)&sQ[kk * 128 + ty * 8 + 4];
            float4 b0 = *(float4*)&sK[kk * 128 + tx * 8];
            float4 b1 = *(float4*)&sK[kk * 128 + tx * 8 + 4];
            float a[8] = {a0.x, a0.y, a0.z, a0.w, a1.x, a1.y, a1.z, a1.w};
            float bb2[8] = {b0.x, b0.y, b0.z, b0.w, b1.x, b1.y, b1.z, b1.w};
#pragma unroll
            for (int i = 0; i < 8; i++)
#pragma unroll
                for (int j = 0; j < 8; j++) acc[i][j] += a[i] * bb2[j];
        }

        // gate with lambda (per-key)
        float lamv[8];
#pragma unroll
        for (int j = 0; j < 8; j++) lamv[j] = slam[kt * KT + tx * 8 + j];
#pragma unroll
        for (int i = 0; i < 8; i++)
#pragma unroll
            for (int j = 0; j < 8; j++) acc[i][j] *= lamv[j];

        // online softmax update (row groups of 16 lanes share a row set)
#pragma unroll
        for (int i = 0; i < 8; i++) {
            float tm = acc[i][0];
#pragma unroll
            for (int j = 1; j < 8; j++) tm = fmaxf(tm, acc[i][j]);
#pragma unroll
            for (int s = 1; s < 16; s <<= 1)
                tm = fmaxf(tm, __shfl_xor_sync(0xffffffffu, tm, s));
            float mnew = fmaxf(mrow[i], tm);
            float corr = __expf(mrow[i] - mnew);
            float rs = 0.0f;
#pragma unroll
            for (int j = 0; j < 8; j++) {
                float p = __expf(acc[i][j] - mnew);
                acc[i][j] = p;
                rs += p;
            }
#pragma unroll
            for (int s = 1; s < 16; s <<= 1)
                rs += __shfl_xor_sync(0xffffffffu, rs, s);
            lrow[i] = lrow[i] * corr + rs;
            mrow[i] = mnew;
#pragma unroll
            for (int c = 0; c < 4; c++) O[i][c] *= corr;
        }

        // store P
#pragma unroll
        for (int i = 0; i < 8; i++) {
            *(float4*)&sP[(ty * 8 + i) * 128 + tx * 8] =
                make_float4(acc[i][0], acc[i][1], acc[i][2], acc[i][3]);
            *(float4*)&sP[(ty * 8 + i) * 128 + tx * 8 + 4] =
                make_float4(acc[i][4], acc[i][5], acc[i][6], acc[i][7]);
        }
        __syncthreads();

        // O += P @ V    rows ty*8+i, cols tx*4..tx*4+3
#pragma unroll 2
        for (int kk = 0; kk < 128; kk += 4) {
            float4 v0 = *(float4*)&sV[(kk + 0) * 64 + tx * 4];
            float4 v1 = *(float4*)&sV[(kk + 1) * 64 + tx * 4];
            float4 v2 = *(float4*)&sV[(kk + 2) * 64 + tx * 4];
            float4 v3 = *(float4*)&sV[(kk + 3) * 64 + tx * 4];
#pragma unroll
            for (int i = 0; i < 8; i++) {
                float4 p = *(float4*)&sP[(ty * 8 + i) * 128 + kk];
                O[i][0] += p.x * v0.x + p.y * v1.x + p.z * v2.x + p.w * v3.x;
                O[i][1] += p.x * v0.y + p.y * v1.y + p.z * v2.y + p.w * v3.y;
                O[i][2] += p.x * v0.z + p.y * v1.z + p.z * v2.z + p.w * v3.z;
                O[i][3] += p.x * v0.w + p.y * v1.w + p.z * v2.w + p.w * v3.w;
            }
        }
    }

    // epilogue: normalize and write to [B,T,C] with head offset
#pragma unroll
    for (int i = 0; i < 8; i++) {
        float inv = 1.0f / lrow[i];
        int t = chunk * CS + qt * QT + ty * 8 + i;
        float* dst = g_attn + ((size_t)b * SEQ + t) * CDIM + h * DH + tx * 4;
        *(float4*)dst = make_float4(O[i][0] * inv, O[i][1] * inv,
                                    O[i][2] * inv, O[i][3] * inv);
    }
}

// ----------------------------------------------------------------------------
// Stage 4: out GEMM.  Y[m,n] = sum_k A[m,k]*Wout[n,k] + bout[n]
// M=16384, N=1024, K=1024
// ----------------------------------------------------------------------------
__global__ __launch_bounds__(256) void out_gemm(const float* __restrict__ Wout,
                                                const float* __restrict__ bout,
                                                float* __restrict__ Y) {
    __shared__ float As[BK][BM];
    __shared__ float Bs[BK][BN];
    const int tid = threadIdx.x;
    const int ty = tid >> 4, tx = tid & 15;
    const int bm = blockIdx.y * BM;
    const int bn = blockIdx.x * BN;
    const float* A = g_attn;

    float acc[8][8];
#pragma unroll
    for (int i = 0; i < 8; i++)
#pragma unroll
        for (int j = 0; j < 8; j++) acc[i][j] = 0.0f;

    for (int k0 = 0; k0 < CDIM; k0 += BK) {
#pragma unroll
        for (int l = 0; l < 2; l++) {
            int idx = tid + l * 256;
            int m = idx >> 2;
            int k4 = idx & 3;
            float4 va = *(const float4*)(A + (size_t)(bm + m) * CDIM + k0 + k4 * 4);
            As[k4 * 4 + 0][m] = va.x; As[k4 * 4 + 1][m] = va.y;
            As[k4 * 4 + 2][m] = va.z; As[k4 * 4 + 3][m] = va.w;
            float4 vb = *(const float4*)(Wout + (size_t)(bn + m) * CDIM + k0 + k4 * 4);
            Bs[k4 * 4 + 0][m] = vb.x; Bs[k4 * 4 + 1][m] = vb.y;
            Bs[k4 * 4 + 2][m] = vb.z; Bs[k4 * 4 + 3][m] = vb.w;
        }
        __syncthreads();
#pragma unroll 4
        for (int kk = 0; kk < BK; kk++) {
            float4 a0 = *(float4*)&As[kk][ty * 8];
            float4 a1 = *(float4*)&As[kk][ty * 8 + 4];
            float4 b0 = *(float4*)&Bs[kk][tx * 8];
            float4 b1 = *(float4*)&Bs[kk][tx * 8 + 4];
            float a[8] = {a0.x, a0.y, a0.z, a0.w, a1.x, a1.y, a1.z, a1.w};
            float b[8] = {b0.x, b0.y, b0.z, b0.w, b1.x, b1.y, b1.z, b1.w};
#pragma unroll
            for (int i = 0; i < 8; i++)
#pragma unroll
                for (int j = 0; j < 8; j++) acc[i][j] += a[i] * b[j];
        }
        __syncthreads();
    }

#pragma unroll
    for (int i = 0; i < 8; i++) {
        int m = bm + ty * 8 + i;
#pragma unroll
        for (int jg = 0; jg < 2; jg++) {
            int n0 = bn + tx * 8 + jg * 4;
            float4 bv = *(const float4*)(bout + n0);
            float4 v = make_float4(acc[i][jg * 4 + 0] + bv.x, acc[i][jg * 4 + 1] + bv.y,
                                   acc[i][jg * 4 + 2] + bv.z, acc[i][jg * 4 + 3] + bv.w);
            *(float4*)(Y + (size_t)m * CDIM + n0) = v;
        }
    }
}

// ----------------------------------------------------------------------------
// Launcher
// ----------------------------------------------------------------------------
extern "C" void kernel_launch(void* const* d_in, const int* in_sizes, int n_in,
                              void* d_out, int out_size) {
    const float* x    = (const float*)d_in[0];
    const float* Wqkv = (const float*)d_in[1];
    const float* Wout = (const float*)d_in[2];
    const float* bout = (const float*)d_in[3];
    const float* Wl1  = (const float*)d_in[4];
    const float* bl1  = (const float*)d_in[5];
    const float* Wl2  = (const float*)d_in[6];
    const float* bl2  = (const float*)d_in[7];
    float* out = (float*)d_out;

    cudaFuncSetAttribute(attn_kernel, cudaFuncAttributeMaxDynamicSharedMemorySize,
                         ATTN_SMEM_BYTES);

    lam_kernel<<<SEQ / 256, 256>>>(Wl1, bl1, Wl2, bl2);
    qkv_gemm<<<dim3(3 * CDIM / BN, M_TOT / BM), 256>>>(x, Wqkv);
    attn_kernel<<<BATCH * HEADS * NCHUNK * (CS / QT), 256, ATTN_SMEM_BYTES>>>();
    out_gemm<<<dim3(CDIM / BN, M_TOT / BM), 256>>>(Wout, bout, out);
}

// round 2
// speedup vs baseline: 1.3447x; 1.3447x over previous
#include <cuda_runtime.h>
#include <cuda_bf16.h>
#include <cuda_pipeline.h>
#include <mma.h>
#include <math.h>

using namespace nvcuda;

// ============================================================================
// LogLinearAttention  (B=4, T=4096, C=1024, H=16, dh=64, nc=8, cs=512)
// R2: dense GEMMs (qkv, out) moved to TF32 wmma tensor cores with cp.async
//     double buffering. Attention stays fp32 SIMT (next target).
// ============================================================================

#define BATCH 4
#define SEQ   4096
#define CDIM  1024
#define HEADS 16
#define DH    64
#define NCHUNK 8
#define CS    512
#define QT    128
#define KT    128
#define M_TOT (BATCH * SEQ)

__device__ float g_q[(size_t)BATCH * HEADS * SEQ * DH];
__device__ float g_k[(size_t)BATCH * HEADS * SEQ * DH];
__device__ float g_v[(size_t)BATCH * HEADS * SEQ * DH];
__device__ float g_attn[(size_t)BATCH * SEQ * CDIM];
__device__ float g_lam[HEADS * SEQ];

// ----------------------------------------------------------------------------
// Stage 1: lambda gates
// ----------------------------------------------------------------------------
__global__ void lam_kernel(const float* __restrict__ Wl1, const float* __restrict__ bl1,
                           const float* __restrict__ Wl2, const float* __restrict__ bl2) {
    int t = blockIdx.x * blockDim.x + threadIdx.x;
    if (t >= SEQ) return;
    float lp = logf((float)t + 1.0f);
    float h1[64];
#pragma unroll
    for (int u = 0; u < 64; u++) {
        float v = lp * Wl1[u] + bl1[u];
        h1[u] = v > 0.0f ? v : 0.0f;
    }
#pragma unroll
    for (int h = 0; h < HEADS; h++) {
        float s = bl2[h];
#pragma unroll
        for (int u = 0; u < 64; u++) s += h1[u] * Wl2[h * 64 + u];
        g_lam[h * SEQ + t] = 1.0f / (1.0f + expf(-s));
    }
}

// ----------------------------------------------------------------------------
// TF32 wmma GEMM tiles: BM=128, BN=128, BK=32, 256 threads (8 warps).
// Warp grid 4x2: each warp owns a 32x64 output tile = 2x4 wmma 16x16 tiles.
// smem per stage: A[128][36] + B[128][36]; 2 stages (cp.async double buffer).
// C[m,n] = sum_k A[m,k] * W[n,k]  (both operands K-contiguous rows)
// ----------------------------------------------------------------------------
#define GBM 128
#define GBN 128
#define GBK 32
#define LDS_PAD 36                       // 32 + 4, keeps 16B alignment
#define STAGE_FLOATS (GBM * LDS_PAD + GBN * LDS_PAD)   // 9216
#define GEMM_SMEM_BYTES (2 * STAGE_FLOATS * 4)         // 73728
#define EPI_LD 132                       // 128+4 for out-gemm staging

__device__ __forceinline__ void load_stage(float* As, float* Bs,
                                           const float* __restrict__ Ag,
                                           const float* __restrict__ Bg,
                                           int bm, int bn, int k0, int tid) {
    // 1024 float4 per operand per stage; 256 threads x 4 each
#pragma unroll
    for (int i = 0; i < 4; i++) {
        int idx = tid + i * 256;          // 0..1023
        int row = idx >> 3;               // 0..127
        int c4  = idx & 7;                // 0..7
        __pipeline_memcpy_async(&As[row * LDS_PAD + c4 * 4],
                                Ag + (size_t)(bm + row) * CDIM + k0 + c4 * 4, 16);
        __pipeline_memcpy_async(&Bs[row * LDS_PAD + c4 * 4],
                                Bg + (size_t)(bn + row) * CDIM + k0 + c4 * 4, 16);
    }
}

template <typename FragA, typename FragB, typename FragC>
__device__ __forceinline__ void compute_stage(const float* As, const float* Bs,
                                              FragC acc[2][4], int wmoff, int wnoff) {
#pragma unroll
    for (int ks = 0; ks < GBK / 8; ks++) {
        FragA af[2];
        FragB bf[4];
#pragma unroll
        for (int i = 0; i < 2; i++) {
            wmma::load_matrix_sync(af[i], &As[(wmoff + i * 16) * LDS_PAD + ks * 8], LDS_PAD);
#pragma unroll
            for (int e = 0; e < af[i].num_elements; e++)
                af[i].x[e] = wmma::__float_to_tf32(af[i].x[e]);
        }
#pragma unroll
        for (int j = 0; j < 4; j++) {
            wmma::load_matrix_sync(bf[j], &Bs[(wnoff + j * 16) * LDS_PAD + ks * 8], LDS_PAD);
#pragma unroll
            for (int e = 0; e < bf[j].num_elements; e++)
                bf[j].x[e] = wmma::__float_to_tf32(bf[j].x[e]);
        }
#pragma unroll
        for (int i = 0; i < 2; i++)
#pragma unroll
            for (int j = 0; j < 4; j++)
                wmma::mma_sync(acc[i][j], af[i], bf[j], acc[i][j]);
    }
}

// ---- Stage 2: qkv GEMM, N=3072, epilogue scatters into q/k/v [B,H,T,64] ----
__global__ __launch_bounds__(256) void qkv_gemm(const float* __restrict__ X,
                                                const float* __restrict__ W) {
    extern __shared__ float sm[];
    float* stage0 = sm;
    float* stage1 = sm + STAGE_FLOATS;

    const int tid = threadIdx.x;
    const int warp = tid >> 5;
    const int wmoff = (warp >> 1) * 32;
    const int wnoff = (warp & 1) * 64;
    const int bm = blockIdx.y * GBM;
    const int bn = blockIdx.x * GBN;

    typedef wmma::fragment<wmma::matrix_a, 16, 16, 8, wmma::precision::tf32, wmma::row_major> FragA;
    typedef wmma::fragment<wmma::matrix_b, 16, 16, 8, wmma::precision::tf32, wmma::col_major> FragB;
    typedef wmma::fragment<wmma::accumulator, 16, 16, 8, float> FragC;

    FragC acc[2][4];
#pragma unroll
    for (int i = 0; i < 2; i++)
#pragma unroll
        for (int j = 0; j < 4; j++) wmma::fill_fragment(acc[i][j], 0.0f);

    const int NK = CDIM / GBK;  // 32
    load_stage(stage0, stage0 + GBM * LDS_PAD, X, W, bm, bn, 0, tid);
    __pipeline_commit();

    for (int kt = 0; kt < NK; kt++) {
        float* cur = (kt & 1) ? stage1 : stage0;
        float* nxt = (kt & 1) ? stage0 : stage1;
        if (kt + 1 < NK) {
            load_stage(nxt, nxt + GBM * LDS_PAD, X, W, bm, bn, (kt + 1) * GBK, tid);
            __pipeline_commit();
            __pipeline_wait_prior(1);
        } else {
            __pipeline_wait_prior(0);
        }
        __syncthreads();
        compute_stage<FragA, FragB, FragC>(cur, cur + GBM * LDS_PAD, acc, wmoff, wnoff);
        __syncthreads();
    }

    // epilogue: each 16x16 tile lands entirely within one of q/k/v, one head
#pragma unroll
    for (int i = 0; i < 2; i++) {
        int m0 = bm + wmoff + i * 16;
        int b = m0 >> 12;
        int t0 = m0 & 4095;
#pragma unroll
        for (int j = 0; j < 4; j++) {
            int n0 = bn + wnoff + j * 16;
            int which = n0 >> 10;
            int c = n0 & 1023;
            int h = c >> 6, d0 = c & 63;
            size_t off = ((size_t)(b * HEADS + h) * SEQ + t0) * DH + d0;
            if (which == 0) {
#pragma unroll
                for (int e = 0; e < acc[i][j].num_elements; e++) acc[i][j].x[e] *= 0.125f;
                wmma::store_matrix_sync(g_q + off, acc[i][j], DH, wmma::mem_row_major);
            } else if (which == 1) {
                wmma::store_matrix_sync(g_k + off, acc[i][j], DH, wmma::mem_row_major);
            } else {
                wmma::store_matrix_sync(g_v + off, acc[i][j], DH, wmma::mem_row_major);
            }
        }
    }
}

// ---- Stage 4: out GEMM, N=1024, bias epilogue via smem staging ----
__global__ __launch_bounds__(256) void out_gemm(const float* __restrict__ Wout,
                                                const float* __restrict__ bout,
                                                float* __restrict__ Y) {
    extern __shared__ float sm[];
    float* stage0 = sm;
    float* stage1 = sm + STAGE_FLOATS;

    const int tid = threadIdx.x;
    const int warp = tid >> 5;
    const int wmoff = (warp >> 1) * 32;
    const int wnoff = (warp & 1) * 64;
    const int bm = blockIdx.y * GBM;
    const int bn = blockIdx.x * GBN;
    const float* A = g_attn;

    typedef wmma::fragment<wmma::matrix_a, 16, 16, 8, wmma::precision::tf32, wmma::row_major> FragA;
    typedef wmma::fragment<wmma::matrix_b, 16, 16, 8, wmma::precision::tf32, wmma::col_major> FragB;
    typedef wmma::fragment<wmma::accumulator, 16, 16, 8, float> FragC;

    FragC acc[2][4];
#pragma unroll
    for (int i = 0; i < 2; i++)
#pragma unroll
        for (int j = 0; j < 4; j++) wmma::fill_fragment(acc[i][j], 0.0f);

    const int NK = CDIM / GBK;
    load_stage(stage0, stage0 + GBM * LDS_PAD, A, Wout, bm, bn, 0, tid);
    __pipeline_commit();

    for (int kt = 0; kt < NK; kt++) {
        float* cur = (kt & 1) ? stage1 : stage0;
        float* nxt = (kt & 1) ? stage0 : stage1;
        if (kt + 1 < NK) {
            load_stage(nxt, nxt + GBM * LDS_PAD, A, Wout, bm, bn, (kt + 1) * GBK, tid);
            __pipeline_commit();
            __pipeline_wait_prior(1);
        } else {
            __pipeline_wait_prior(0);
        }
        __syncthreads();
        compute_stage<FragA, FragB, FragC>(cur, cur + GBM * LDS_PAD, acc, wmoff, wnoff);
        __syncthreads();
    }

    // stage 128x128 result tile in smem (reuses pipeline buffers), add bias
#pragma unroll
    for (int i = 0; i < 2; i++)
#pragma unroll
        for (int j = 0; j < 4; j++)
            wmma::store_matrix_sync(&sm[(wmoff + i * 16) * EPI_LD + wnoff + j * 16],
                                    acc[i][j], EPI_LD, wmma::mem_row_major);
    __syncthreads();

#pragma unroll
    for (int l = 0; l < 16; l++) {
        int idx = tid + l * 256;          // 0..4095 float4s
        int row = idx >> 5;               // 0..127
        int c4 = idx & 31;                // 0..31
        float4 v = *(float4*)&sm[row * EPI_LD + c4 * 4];
        float4 bv = *(const float4*)(bout + bn + c4 * 4);
        v.x += bv.x; v.y += bv.y; v.z += bv.z; v.w += bv.w;
        *(float4*)(Y + (size_t)(bm + row) * CDIM + bn + c4 * 4) = v;
    }
}

// ----------------------------------------------------------------------------
// Stage 3: chunked attention (unchanged fp32 SIMT, flash-style)
// ----------------------------------------------------------------------------
#define ATTN_SMEM_FLOATS (64 * 128 + 64 * 128 + 128 * 64 + 128 * 128 + 512)
#define ATTN_SMEM_BYTES (ATTN_SMEM_FLOATS * 4)

__global__ __launch_bounds__(256) void attn_kernel() {
    extern __shared__ float sm[];
    float* sQ = sm;
    float* sK = sQ + 64 * 128;
    float* sV = sK + 64 * 128;
    float* sP = sV + 128 * 64;
    float* slam = sP + 128 * 128;

    const int bx = blockIdx.x;
    const int qt = bx & 3;
    const int chunk = (bx >> 2) & 7;
    const int h = (bx >> 5) & 15;
    const int b = bx >> 9;
    const int tid = threadIdx.x;
    const int ty = tid >> 4, tx = tid & 15;

    const size_t head_base = ((size_t)(b * HEADS + h) * SEQ + chunk * CS) * DH;
    const float* Qg = g_q + head_base + (size_t)qt * QT * DH;
    const float* Kg = g_k + head_base;
    const float* Vg = g_v + head_base;

    for (int j = tid; j < CS; j += 256) slam[j] = g_lam[h * SEQ + chunk * CS + j];

#pragma unroll
    for (int l = 0; l < 8; l++) {
        int idx = tid + l * 256;
        int r = idx >> 4;
        int d4 = idx & 15;
        float4 v = *(const float4*)(Qg + (size_t)r * DH + d4 * 4);
        sQ[(d4 * 4 + 0) * 128 + r] = v.x;
        sQ[(d4 * 4 + 1) * 128 + r] = v.y;
        sQ[(d4 * 4 + 2) * 128 + r] = v.z;
        sQ[(d4 * 4 + 3) * 128 + r] = v.w;
    }

    float O[8][4];
    float mrow[8], lrow[8];
#pragma unroll
    for (int i = 0; i < 8; i++) {
        mrow[i] = -1e30f;
        lrow[i] = 0.0f;
#pragma unroll
        for (int c = 0; c < 4; c++) O[i][c] = 0.0f;
    }

    for (int kt = 0; kt < 4; kt++) {
        __syncthreads();
#pragma unroll
        for (int l = 0; l < 8; l++) {
            int idx = tid + l * 256;
            int r = idx >> 4;
            int d4 = idx & 15;
            float4 vk = *(const float4*)(Kg + ((size_t)kt * KT + r) * DH + d4 * 4);
            sK[(d4 * 4 + 0) * 128 + r] = vk.x;
            sK[(d4 * 4 + 1) * 128 + r] = vk.y;
            sK[(d4 * 4 + 2) * 128 + r] = vk.z;
            sK[(d4 * 4 + 3) * 128 + r] = vk.w;
            float4 vv = *(const float4*)(Vg + ((size_t)kt * KT + r) * DH + d4 * 4);
            *(float4*)(sV + r * 64 + d4 * 4) = vv;
        }
        __syncthreads();

        float acc[8][8];
#pragma unroll
        for (int i = 0; i < 8; i++)
#pragma unroll
            for (int j = 0; j < 8; j++) acc[i][j] = 0.0f;
#pragma unroll 2
        for (int kk = 0; kk < 64; kk++) {
            float4 a0 = *(float4*)&sQ[kk * 128 + ty * 8];
            float4 a1 = *(float4*)&sQ[kk * 128 + ty * 8 + 4];
            float4 b0 = *(float4*)&sK[kk * 128 + tx * 8];
            float4 b1 = *(float4*)&sK[kk * 128 + tx * 8 + 4];
            float a[8] = {a0.x, a0.y, a0.z, a0.w, a1.x, a1.y, a1.z, a1.w};
            float bb2[8] = {b0.x, b0.y, b0.z, b0.w, b1.x, b1.y, b1.z, b1.w};
#pragma unroll
            for (int i = 0; i < 8; i++)
#pragma unroll
                for (int j = 0; j < 8; j++) acc[i][j] += a[i] * bb2[j];
        }

        float lamv[8];
#pragma unroll
        for (int j = 0; j < 8; j++) lamv[j] = slam[kt * KT + tx * 8 + j];
#pragma unroll
        for (int i = 0; i < 8; i++)
#pragma unroll
            for (int j = 0; j < 8; j++) acc[i][j] *= lamv[j];

#pragma unroll
        for (int i = 0; i < 8; i++) {
            float tm = acc[i][0];
#pragma unroll
            for (int j = 1; j < 8; j++) tm = fmaxf(tm, acc[i][j]);
#pragma unroll
            for (int s = 1; s < 16; s <<= 1)
                tm = fmaxf(tm, __shfl_xor_sync(0xffffffffu, tm, s));
            float mnew = fmaxf(mrow[i], tm);
            float corr = __expf(mrow[i] - mnew);
            float rs = 0.0f;
#pragma unroll
            for (int j = 0; j < 8; j++) {
                float p = __expf(acc[i][j] - mnew);
                acc[i][j] = p;
                rs += p;
            }
#pragma unroll
            for (int s = 1; s < 16; s <<= 1)
                rs += __shfl_xor_sync(0xffffffffu, rs, s);
            lrow[i] = lrow[i] * corr + rs;
            mrow[i] = mnew;
#pragma unroll
            for (int c = 0; c < 4; c++) O[i][c] *= corr;
        }

#pragma unroll
        for (int i = 0; i < 8; i++) {
            *(float4*)&sP[(ty * 8 + i) * 128 + tx * 8] =
                make_float4(acc[i][0], acc[i][1], acc[i][2], acc[i][3]);
            *(float4*)&sP[(ty * 8 + i) * 128 + tx * 8 + 4] =
                make_float4(acc[i][4], acc[i][5], acc[i][6], acc[i][7]);
        }
        __syncthreads();

#pragma unroll 2
        for (int kk = 0; kk < 128; kk += 4) {
            float4 v0 = *(float4*)&sV[(kk + 0) * 64 + tx * 4];
            float4 v1 = *(float4*)&sV[(kk + 1) * 64 + tx * 4];
            float4 v2 = *(float4*)&sV[(kk + 2) * 64 + tx * 4];
            float4 v3 = *(float4*)&sV[(kk + 3) * 64 + tx * 4];
#pragma unroll
            for (int i = 0; i < 8; i++) {
                float4 p = *(float4*)&sP[(ty * 8 + i) * 128 + kk];
                O[i][0] += p.x * v0.x + p.y * v1.x + p.z * v2.x + p.w * v3.x;
                O[i][1] += p.x * v0.y + p.y * v1.y + p.z * v2.y + p.w * v3.y;
                O[i][2] += p.x * v0.z + p.y * v1.z + p.z * v2.z + p.w * v3.z;
                O[i][3] += p.x * v0.w + p.y * v1.w + p.z * v2.w + p.w * v3.w;
            }
        }
    }

#pragma unroll
    for (int i = 0; i < 8; i++) {
        float inv = 1.0f / lrow[i];
        int t = chunk * CS + qt * QT + ty * 8 + i;
        float* dst = g_attn + ((size_t)b * SEQ + t) * CDIM + h * DH + tx * 4;
        *(float4*)dst = make_float4(O[i][0] * inv, O[i][1] * inv,
                                    O[i][2] * inv, O[i][3] * inv);
    }
}

// ----------------------------------------------------------------------------
// Launcher
// ----------------------------------------------------------------------------
extern "C" void kernel_launch(void* const* d_in, const int* in_sizes, int n_in,
                              void* d_out, int out_size) {
    const float* x    = (const float*)d_in[0];
    const float* Wqkv = (const float*)d_in[1];
    const float* Wout = (const float*)d_in[2];
    const float* bout = (const float*)d_in[3];
    const float* Wl1  = (const float*)d_in[4];
    const float* bl1  = (const float*)d_in[5];
    const float* Wl2  = (const float*)d_in[6];
    const float* bl2  = (const float*)d_in[7];
    float* out = (float*)d_out;

    static bool attr_set = false;
    if (!attr_set) {
        cudaFuncSetAttribute(attn_kernel, cudaFuncAttributeMaxDynamicSharedMemorySize,
                             ATTN_SMEM_BYTES);
        cudaFuncSetAttribute(qkv_gemm, cudaFuncAttributeMaxDynamicSharedMemorySize,
                             GEMM_SMEM_BYTES);
        cudaFuncSetAttribute(out_gemm, cudaFuncAttributeMaxDynamicSharedMemorySize,
                             GEMM_SMEM_BYTES);
        attr_set = true;
    }

    lam_kernel<<<SEQ / 256, 256>>>(Wl1, bl1, Wl2, bl2);
    qkv_gemm<<<dim3(3 * CDIM / GBN, M_TOT / GBM), 256, GEMM_SMEM_BYTES>>>(x, Wqkv);
    attn_kernel<<<BATCH * HEADS * NCHUNK * (CS / QT), 256, ATTN_SMEM_BYTES>>>();
    out_gemm<<<dim3(CDIM / GBN, M_TOT / GBM), 256, GEMM_SMEM_BYTES>>>(Wout, bout, out);
}

// round 4
// speedup vs baseline: 2.1955x; 1.6328x over previous
#include <cuda_runtime.h>
#include <cuda_bf16.h>
#include <cuda_pipeline.h>
#include <math.h>
#include <cstdint>

// ============================================================================
// LogLinearAttention  (B=4, T=4096, C=1024, H=16, dh=64, nc=8, cs=512)
// R4: harness targets plain sm_100 => tcgen05 unavailable. Dense GEMMs use
//     raw mma.sync m16n8k8 TF32 (sm_80+ ISA) with pre-rounded tf32 operands,
//     3-stage cp.async pipeline, 2 CTAs/SM. Attention stays fp32 SIMT.
// ============================================================================

#define BATCH 4
#define SEQ   4096
#define CDIM  1024
#define HEADS 16
#define DH    64
#define CS    512
#define QT    128
#define KT    128
#define M_TOT (BATCH * SEQ)

__device__ float g_q[(size_t)BATCH * HEADS * SEQ * DH];
__device__ float g_k[(size_t)BATCH * HEADS * SEQ * DH];
__device__ float g_v[(size_t)BATCH * HEADS * SEQ * DH];
__device__ float g_attn[(size_t)M_TOT * CDIM];     // tf32-rounded fp32
__device__ float g_lam[HEADS * SEQ];
__device__ float g_x32[(size_t)M_TOT * CDIM];      // tf32-rounded copies
__device__ float g_wqkv32[(size_t)3 * CDIM * CDIM];
__device__ float g_wout32[(size_t)CDIM * CDIM];

// ---------------------------------------------------------------------------
// tf32 rounding prepass:  fp32 -> tf32 (rna) stored as fp32 bit patterns
// ---------------------------------------------------------------------------
__global__ void round_tf32(const float4* __restrict__ src, uint4* __restrict__ dst, int n4) {
    int i = blockIdx.x * 256 + threadIdx.x;
    if (i >= n4) return;
    float4 v = src[i];
    uint4 o;
    asm("cvt.rna.tf32.f32 %0, %1;" : "=r"(o.x) : "f"(v.x));
    asm("cvt.rna.tf32.f32 %0, %1;" : "=r"(o.y) : "f"(v.y));
    asm("cvt.rna.tf32.f32 %0, %1;" : "=r"(o.z) : "f"(v.z));
    asm("cvt.rna.tf32.f32 %0, %1;" : "=r"(o.w) : "f"(v.w));
    dst[i] = o;
}

// ---------------------------------------------------------------------------
// Stage 1: lambda gates
// ---------------------------------------------------------------------------
__global__ void lam_kernel(const float* __restrict__ Wl1, const float* __restrict__ bl1,
                           const float* __restrict__ Wl2, const float* __restrict__ bl2) {
    int t = blockIdx.x * blockDim.x + threadIdx.x;
    if (t >= SEQ) return;
    float lp = logf((float)t + 1.0f);
    float h1[64];
#pragma unroll
    for (int u = 0; u < 64; u++) {
        float v = lp * Wl1[u] + bl1[u];
        h1[u] = v > 0.0f ? v : 0.0f;
    }
#pragma unroll
    for (int h = 0; h < HEADS; h++) {
        float s = bl2[h];
#pragma unroll
        for (int u = 0; u < 64; u++) s += h1[u] * Wl2[h * 64 + u];
        g_lam[h * SEQ + t] = 1.0f / (1.0f + expf(-s));
    }
}

// ---------------------------------------------------------------------------
// TF32 mma.sync GEMM.  C[m,n] = sum_k A[m,k]*B[n,k]
// Tile 128x128x32, 256 threads (8 warps, 2x4), warp tile 64x32 = 4x4 m16n8.
// 3-stage cp.async. Operands pre-rounded to tf32.
// mode 0: qkv scatter (q*0.125).  mode 1: +bias -> Y.
// ---------------------------------------------------------------------------
#define GBM 128
#define GBN 128
#define GBK 32
#define STRIDE 36                       // 32 + 4 floats, 16B-aligned rows
#define OPER_BYTES (128 * STRIDE * 4)   // 18432 per operand
#define STAGE_BYTES (2 * OPER_BYTES)    // 36864
#define NSTAGE 3
#define GEMM_SMEM (NSTAGE * STAGE_BYTES)  // 110592
#define NKIT (CDIM / GBK)               // 32

__device__ __forceinline__ void mma_tf32(float* c, const uint32_t* a, const uint32_t* b) {
    asm volatile(
        "mma.sync.aligned.m16n8k8.row.col.f32.tf32.tf32.f32 "
        "{%0,%1,%2,%3}, {%4,%5,%6,%7}, {%8,%9}, {%0,%1,%2,%3};"
        : "+f"(c[0]), "+f"(c[1]), "+f"(c[2]), "+f"(c[3])
        : "r"(a[0]), "r"(a[1]), "r"(a[2]), "r"(a[3]), "r"(b[0]), "r"(b[1]));
}

__device__ __forceinline__ void ld_gemm_stage(char* st, const float* __restrict__ A,
                                              const float* __restrict__ B,
                                              int bm, int bn, int k0, int tid) {
#pragma unroll
    for (int i = 0; i < 4; i++) {
        int idx = tid + i * 256;          // 0..1023
        int row = idx >> 3;
        int c4  = idx & 7;
        __pipeline_memcpy_async(st + (row * STRIDE + c4 * 4) * 4,
                                A + (size_t)(bm + row) * CDIM + k0 + c4 * 4, 16);
        __pipeline_memcpy_async(st + OPER_BYTES + (row * STRIDE + c4 * 4) * 4,
                                B + (size_t)(bn + row) * CDIM + k0 + c4 * 4, 16);
    }
}

__global__ __launch_bounds__(256, 2) void gemm_mma(const float* __restrict__ A,
                                                   const float* __restrict__ B,
                                                   const float* __restrict__ bias,
                                                   float* __restrict__ Y, int mode) {
    extern __shared__ char smc[];
    const int tid = threadIdx.x;
    const int w = tid >> 5, lane = tid & 31;
    const int g = lane >> 2, tg = lane & 3;
    const int mo = (w >> 2) * 64;        // warp m offset in tile
    const int no = (w & 3) * 32;         // warp n offset in tile
    const int bm = blockIdx.y * GBM;
    const int bn = blockIdx.x * GBN;

    float acc[4][4][4];
#pragma unroll
    for (int mi = 0; mi < 4; mi++)
#pragma unroll
        for (int ni = 0; ni < 4; ni++)
#pragma unroll
            for (int e = 0; e < 4; e++) acc[mi][ni][e] = 0.0f;

    ld_gemm_stage(smc, A, B, bm, bn, 0, tid);
    __pipeline_commit();
    ld_gemm_stage(smc + STAGE_BYTES, A, B, bm, bn, GBK, tid);
    __pipeline_commit();

    int buf_next = 2;
    for (int it = 0; it < NKIT; it++) {
        if (it + 2 < NKIT) {
            ld_gemm_stage(smc + buf_next * STAGE_BYTES, A, B, bm, bn, (it + 2) * GBK, tid);
            __pipeline_commit();
            __pipeline_wait_prior(2);
            buf_next = (buf_next + 1) % NSTAGE;
        } else if (it + 1 < NKIT) {
            __pipeline_wait_prior(1);
        } else {
            __pipeline_wait_prior(0);
        }
        __syncthreads();

        const uint32_t* sA = (const uint32_t*)(smc + (it % NSTAGE) * STAGE_BYTES);
        const uint32_t* sB = (const uint32_t*)(smc + (it % NSTAGE) * STAGE_BYTES + OPER_BYTES);

#pragma unroll
        for (int ks = 0; ks < 4; ks++) {
            const int k = ks * 8;
            uint32_t bfr[4][2];
#pragma unroll
            for (int ni = 0; ni < 4; ni++) {
                const int nb = no + ni * 8 + g;
                bfr[ni][0] = sB[nb * STRIDE + k + tg];
                bfr[ni][1] = sB[nb * STRIDE + k + tg + 4];
            }
#pragma unroll
            for (int mi = 0; mi < 4; mi++) {
                const int rb = mo + mi * 16 + g;
                uint32_t afr[4];
                afr[0] = sA[rb * STRIDE + k + tg];
                afr[1] = sA[(rb + 8) * STRIDE + k + tg];
                afr[2] = sA[rb * STRIDE + k + tg + 4];
                afr[3] = sA[(rb + 8) * STRIDE + k + tg + 4];
#pragma unroll
                for (int ni = 0; ni < 4; ni++)
                    mma_tf32(acc[mi][ni], afr, bfr[ni]);
            }
        }
        __syncthreads();
    }

    // epilogue
#pragma unroll
    for (int mi = 0; mi < 4; mi++) {
        const int m0 = bm + mo + mi * 16 + g;
#pragma unroll
        for (int ni = 0; ni < 4; ni++) {
            const int n = bn + no + ni * 8 + tg * 2;
            const float* c = acc[mi][ni];
            if (mode == 0) {
                const int which = n >> 10;
                const int cr = n & 1023;
                const int h = cr >> 6, d = cr & 63;
                float scale = 1.0f;
                float* dst;
                if (which == 0) { dst = g_q; scale = 0.125f; }
                else if (which == 1) dst = g_k;
                else dst = g_v;
#pragma unroll
                for (int rr = 0; rr < 2; rr++) {
                    const int m = m0 + rr * 8;
                    const int b = m >> 12, t = m & 4095;
                    const size_t off = ((size_t)(b * HEADS + h) * SEQ + t) * DH + d;
                    *(float2*)(dst + off) = make_float2(c[rr * 2] * scale, c[rr * 2 + 1] * scale);
                }
            } else {
                const float2 bv = *(const float2*)(bias + n);
#pragma unroll
                for (int rr = 0; rr < 2; rr++) {
                    const int m = m0 + rr * 8;
                    *(float2*)(Y + (size_t)m * CDIM + n) =
                        make_float2(c[rr * 2] + bv.x, c[rr * 2 + 1] + bv.y);
                }
            }
        }
    }
}

// ---------------------------------------------------------------------------
// Stage 3: chunked attention, fp32 SIMT; epilogue writes tf32-rounded output
// ---------------------------------------------------------------------------
#define ATTN_SMEM_FLOATS (64 * 128 + 64 * 128 + 128 * 64 + 128 * 128 + 512)
#define ATTN_SMEM_BYTES (ATTN_SMEM_FLOATS * 4)

__global__ __launch_bounds__(256) void attn_kernel() {
    extern __shared__ float smf[];
    float* sQ = smf;
    float* sK = sQ + 64 * 128;
    float* sV = sK + 64 * 128;
    float* sP = sV + 128 * 64;
    float* slam = sP + 128 * 128;

    const int bx = blockIdx.x;
    const int qt = bx & 3;
    const int chunk = (bx >> 2) & 7;
    const int h = (bx >> 5) & 15;
    const int b = bx >> 9;
    const int tid = threadIdx.x;
    const int ty = tid >> 4, tx = tid & 15;

    const size_t head_base = ((size_t)(b * HEADS + h) * SEQ + chunk * CS) * DH;
    const float* Qg = g_q + head_base + (size_t)qt * QT * DH;
    const float* Kg = g_k + head_base;
    const float* Vg = g_v + head_base;

    for (int j = tid; j < CS; j += 256) slam[j] = g_lam[h * SEQ + chunk * CS + j];

#pragma unroll
    for (int l = 0; l < 8; l++) {
        int idx = tid + l * 256;
        int r = idx >> 4;
        int d4 = idx & 15;
        float4 v = *(const float4*)(Qg + (size_t)r * DH + d4 * 4);
        sQ[(d4 * 4 + 0) * 128 + r] = v.x;
        sQ[(d4 * 4 + 1) * 128 + r] = v.y;
        sQ[(d4 * 4 + 2) * 128 + r] = v.z;
        sQ[(d4 * 4 + 3) * 128 + r] = v.w;
    }

    float O[8][4];
    float mrow[8], lrow[8];
#pragma unroll
    for (int i = 0; i < 8; i++) {
        mrow[i] = -1e30f;
        lrow[i] = 0.0f;
#pragma unroll
        for (int c = 0; c < 4; c++) O[i][c] = 0.0f;
    }

    for (int kt = 0; kt < 4; kt++) {
        __syncthreads();
#pragma unroll
        for (int l = 0; l < 8; l++) {
            int idx = tid + l * 256;
            int r = idx >> 4;
            int d4 = idx & 15;
            float4 vk = *(const float4*)(Kg + ((size_t)kt * KT + r) * DH + d4 * 4);
            sK[(d4 * 4 + 0) * 128 + r] = vk.x;
            sK[(d4 * 4 + 1) * 128 + r] = vk.y;
            sK[(d4 * 4 + 2) * 128 + r] = vk.z;
            sK[(d4 * 4 + 3) * 128 + r] = vk.w;
            float4 vv = *(const float4*)(Vg + ((size_t)kt * KT + r) * DH + d4 * 4);
            *(float4*)(sV + r * 64 + d4 * 4) = vv;
        }
        __syncthreads();

        float acc[8][8];
#pragma unroll
        for (int i = 0; i < 8; i++)
#pragma unroll
            for (int j = 0; j < 8; j++) acc[i][j] = 0.0f;
#pragma unroll 2
        for (int kk = 0; kk < 64; kk++) {
            float4 a0 = *(float4*)&sQ[kk * 128 + ty * 8];
            float4 a1 = *(float4*)&sQ[kk * 128 + ty * 8 + 4];
            float4 b0 = *(float4*)&sK[kk * 128 + tx * 8];
            float4 b1 = *(float4*)&sK[kk * 128 + tx * 8 + 4];
            float a[8] = {a0.x, a0.y, a0.z, a0.w, a1.x, a1.y, a1.z, a1.w};
            float bb2[8] = {b0.x, b0.y, b0.z, b0.w, b1.x, b1.y, b1.z, b1.w};
#pragma unroll
            for (int i = 0; i < 8; i++)
#pragma unroll
                for (int j = 0; j < 8; j++) acc[i][j] += a[i] * bb2[j];
        }

        float lamv[8];
#pragma unroll
        for (int j = 0; j < 8; j++) lamv[j] = slam[kt * KT + tx * 8 + j];
#pragma unroll
        for (int i = 0; i < 8; i++)
#pragma unroll
            for (int j = 0; j < 8; j++) acc[i][j] *= lamv[j];

#pragma unroll
        for (int i = 0; i < 8; i++) {
            float tm = acc[i][0];
#pragma unroll
            for (int j = 1; j < 8; j++) tm = fmaxf(tm, acc[i][j]);
#pragma unroll
            for (int s = 1; s < 16; s <<= 1)
                tm = fmaxf(tm, __shfl_xor_sync(0xffffffffu, tm, s));
            float mnew = fmaxf(mrow[i], tm);
            float corr = __expf(mrow[i] - mnew);
            float rs = 0.0f;
#pragma unroll
            for (int j = 0; j < 8; j++) {
                float p = __expf(acc[i][j] - mnew);
                acc[i][j] = p;
                rs += p;
            }
#pragma unroll
            for (int s = 1; s < 16; s <<= 1)
                rs += __shfl_xor_sync(0xffffffffu, rs, s);
            lrow[i] = lrow[i] * corr + rs;
            mrow[i] = mnew;
#pragma unroll
            for (int c = 0; c < 4; c++) O[i][c] *= corr;
        }

#pragma unroll
        for (int i = 0; i < 8; i++) {
            *(float4*)&sP[(ty * 8 + i) * 128 + tx * 8] =
                make_float4(acc[i][0], acc[i][1], acc[i][2], acc[i][3]);
            *(float4*)&sP[(ty * 8 + i) * 128 + tx * 8 + 4] =
                make_float4(acc[i][4], acc[i][5], acc[i][6], acc[i][7]);
        }
        __syncthreads();

#pragma unroll 2
        for (int kk = 0; kk < 128; kk += 4) {
            float4 v0 = *(float4*)&sV[(kk + 0) * 64 + tx * 4];
            float4 v1 = *(float4*)&sV[(kk + 1) * 64 + tx * 4];
            float4 v2 = *(float4*)&sV[(kk + 2) * 64 + tx * 4];
            float4 v3 = *(float4*)&sV[(kk + 3) * 64 + tx * 4];
#pragma unroll
            for (int i = 0; i < 8; i++) {
                float4 p = *(float4*)&sP[(ty * 8 + i) * 128 + kk];
                O[i][0] += p.x * v0.x + p.y * v1.x + p.z * v2.x + p.w * v3.x;
                O[i][1] += p.x * v0.y + p.y * v1.y + p.z * v2.y + p.w * v3.y;
                O[i][2] += p.x * v0.z + p.y * v1.z + p.z * v2.z + p.w * v3.z;
                O[i][3] += p.x * v0.w + p.y * v1.w + p.z * v2.w + p.w * v3.w;
            }
        }
    }

    // epilogue: normalize, round to tf32, write [B,T,C]
#pragma unroll
    for (int i = 0; i < 8; i++) {
        float inv = 1.0f / lrow[i];
        int t = chunk * CS + qt * QT + ty * 8 + i;
        float* dst = g_attn + ((size_t)b * SEQ + t) * CDIM + h * DH + tx * 4;
        uint4 o;
        float v0 = O[i][0] * inv, v1 = O[i][1] * inv, v2 = O[i][2] * inv, v3 = O[i][3] * inv;
        asm("cvt.rna.tf32.f32 %0, %1;" : "=r"(o.x) : "f"(v0));
        asm("cvt.rna.tf32.f32 %0, %1;" : "=r"(o.y) : "f"(v1));
        asm("cvt.rna.tf32.f32 %0, %1;" : "=r"(o.z) : "f"(v2));
        asm("cvt.rna.tf32.f32 %0, %1;" : "=r"(o.w) : "f"(v3));
        *(uint4*)dst = o;
    }
}

// ---------------------------------------------------------------------------
// Launcher
// ---------------------------------------------------------------------------
extern "C" void kernel_launch(void* const* d_in, const int* in_sizes, int n_in,
                              void* d_out, int out_size) {
    const float* x    = (const float*)d_in[0];
    const float* Wqkv = (const float*)d_in[1];
    const float* Wout = (const float*)d_in[2];
    const float* bout = (const float*)d_in[3];
    const float* Wl1  = (const float*)d_in[4];
    const float* bl1  = (const float*)d_in[5];
    const float* Wl2  = (const float*)d_in[6];
    const float* bl2  = (const float*)d_in[7];
    float* out = (float*)d_out;

    cudaFuncSetAttribute(attn_kernel, cudaFuncAttributeMaxDynamicSharedMemorySize,
                         ATTN_SMEM_BYTES);
    cudaFuncSetAttribute(gemm_mma, cudaFuncAttributeMaxDynamicSharedMemorySize,
                         GEMM_SMEM);

    float *x32, *w32, *o32, *a32;
    cudaGetSymbolAddress((void**)&x32, g_x32);
    cudaGetSymbolAddress((void**)&w32, g_wqkv32);
    cudaGetSymbolAddress((void**)&o32, g_wout32);
    cudaGetSymbolAddress((void**)&a32, g_attn);

    lam_kernel<<<SEQ / 256, 256>>>(Wl1, bl1, Wl2, bl2);

    {   // tf32 rounding prepasses
        int n4 = M_TOT * CDIM / 4;
        round_tf32<<<(n4 + 255) / 256, 256>>>((const float4*)x, (uint4*)x32, n4);
        n4 = 3 * CDIM * CDIM / 4;
        round_tf32<<<(n4 + 255) / 256, 256>>>((const float4*)Wqkv, (uint4*)w32, n4);
        n4 = CDIM * CDIM / 4;
        round_tf32<<<(n4 + 255) / 256, 256>>>((const float4*)Wout, (uint4*)o32, n4);
    }

    gemm_mma<<<dim3(3 * CDIM / GBN, M_TOT / GBM), 256, GEMM_SMEM>>>(
        x32, w32, nullptr, nullptr, 0);

    attn_kernel<<<BATCH * HEADS * 8 * (CS / QT), 256, ATTN_SMEM_BYTES>>>();

    gemm_mma<<<dim3(CDIM / GBN, M_TOT / GBM), 256, GEMM_SMEM>>>(
        a32, o32, bout, out, 1);
}

// round 5
// speedup vs baseline: 3.3196x; 1.5120x over previous
#include <cuda_runtime.h>
#include <cuda_bf16.h>
#include <cuda_pipeline.h>
#include <math.h>
#include <cstdint>

// ============================================================================
// LogLinearAttention  (B=4, T=4096, C=1024, H=16, dh=64, nc=8, cs=512)
// R5: attention moved to mma.sync m16n8k16 bf16 with hi/lo split (fp32-like
//     precision). qkv epilogue emits q/k bf16 hi/lo + v transposed bf16 hi/lo.
//     Dense GEMMs stay tf32 mma.sync.
// ============================================================================

#define BATCH 4
#define SEQ   4096
#define CDIM  1024
#define HEADS 16
#define DH    64
#define CS    512
#define QT    128
#define M_TOT (BATCH * SEQ)

__device__ float g_attn[(size_t)M_TOT * CDIM];     // tf32-rounded fp32
__device__ float g_lam[HEADS * SEQ];
__device__ float g_x32[(size_t)M_TOT * CDIM];      // tf32-rounded copies
__device__ float g_wqkv32[(size_t)3 * CDIM * CDIM];
__device__ float g_wout32[(size_t)CDIM * CDIM];

// bf16 hi/lo tensors for attention
#define QKV_ELEMS ((size_t)BATCH * HEADS * SEQ * DH)
__device__ __nv_bfloat16 g_qh[QKV_ELEMS];
__device__ __nv_bfloat16 g_ql[QKV_ELEMS];
__device__ __nv_bfloat16 g_kh[QKV_ELEMS];
__device__ __nv_bfloat16 g_kl[QKV_ELEMS];
__device__ __nv_bfloat16 g_vth[QKV_ELEMS];         // [B,H,64,T] transposed
__device__ __nv_bfloat16 g_vtl[QKV_ELEMS];

// ---------------------------------------------------------------------------
// tf32 rounding prepass
// ---------------------------------------------------------------------------
__global__ void round_tf32(const float4* __restrict__ src, uint4* __restrict__ dst, int n4) {
    int i = blockIdx.x * 256 + threadIdx.x;
    if (i >= n4) return;
    float4 v = src[i];
    uint4 o;
    asm("cvt.rna.tf32.f32 %0, %1;" : "=r"(o.x) : "f"(v.x));
    asm("cvt.rna.tf32.f32 %0, %1;" : "=r"(o.y) : "f"(v.y));
    asm("cvt.rna.tf32.f32 %0, %1;" : "=r"(o.z) : "f"(v.z));
    asm("cvt.rna.tf32.f32 %0, %1;" : "=r"(o.w) : "f"(v.w));
    dst[i] = o;
}

// ---------------------------------------------------------------------------
// Stage 1: lambda gates
// ---------------------------------------------------------------------------
__global__ void lam_kernel(const float* __restrict__ Wl1, const float* __restrict__ bl1,
                           const float* __restrict__ Wl2, const float* __restrict__ bl2) {
    int t = blockIdx.x * blockDim.x + threadIdx.x;
    if (t >= SEQ) return;
    float lp = logf((float)t + 1.0f);
    float h1[64];
#pragma unroll
    for (int u = 0; u < 64; u++) {
        float v = lp * Wl1[u] + bl1[u];
        h1[u] = v > 0.0f ? v : 0.0f;
    }
#pragma unroll
    for (int h = 0; h < HEADS; h++) {
        float s = bl2[h];
#pragma unroll
        for (int u = 0; u < 64; u++) s += h1[u] * Wl2[h * 64 + u];
        g_lam[h * SEQ + t] = 1.0f / (1.0f + expf(-s));
    }
}

// ---------------------------------------------------------------------------
// TF32 mma.sync GEMM (unchanged from R4 except mode-0 epilogue).
// ---------------------------------------------------------------------------
#define GBM 128
#define GBN 128
#define GBK 32
#define STRIDE 36
#define OPER_BYTES (128 * STRIDE * 4)
#define STAGE_BYTES (2 * OPER_BYTES)
#define NSTAGE 3
#define GEMM_SMEM (NSTAGE * STAGE_BYTES)
#define NKIT (CDIM / GBK)

__device__ __forceinline__ void mma_tf32(float* c, const uint32_t* a, const uint32_t* b) {
    asm volatile(
        "mma.sync.aligned.m16n8k8.row.col.f32.tf32.tf32.f32 "
        "{%0,%1,%2,%3}, {%4,%5,%6,%7}, {%8,%9}, {%0,%1,%2,%3};"
        : "+f"(c[0]), "+f"(c[1]), "+f"(c[2]), "+f"(c[3])
        : "r"(a[0]), "r"(a[1]), "r"(a[2]), "r"(a[3]), "r"(b[0]), "r"(b[1]));
}

__device__ __forceinline__ void ld_gemm_stage(char* st, const float* __restrict__ A,
                                              const float* __restrict__ B,
                                              int bm, int bn, int k0, int tid) {
#pragma unroll
    for (int i = 0; i < 4; i++) {
        int idx = tid + i * 256;
        int row = idx >> 3;
        int c4  = idx & 7;
        __pipeline_memcpy_async(st + (row * STRIDE + c4 * 4) * 4,
                                A + (size_t)(bm + row) * CDIM + k0 + c4 * 4, 16);
        __pipeline_memcpy_async(st + OPER_BYTES + (row * STRIDE + c4 * 4) * 4,
                                B + (size_t)(bn + row) * CDIM + k0 + c4 * 4, 16);
    }
}

__global__ __launch_bounds__(256, 2) void gemm_mma(const float* __restrict__ A,
                                                   const float* __restrict__ B,
                                                   const float* __restrict__ bias,
                                                   float* __restrict__ Y, int mode) {
    extern __shared__ char smc[];
    const int tid = threadIdx.x;
    const int w = tid >> 5, lane = tid & 31;
    const int g = lane >> 2, tg = lane & 3;
    const int mo = (w >> 2) * 64;
    const int no = (w & 3) * 32;
    const int bm = blockIdx.y * GBM;
    const int bn = blockIdx.x * GBN;

    float acc[4][4][4];
#pragma unroll
    for (int mi = 0; mi < 4; mi++)
#pragma unroll
        for (int ni = 0; ni < 4; ni++)
#pragma unroll
            for (int e = 0; e < 4; e++) acc[mi][ni][e] = 0.0f;

    ld_gemm_stage(smc, A, B, bm, bn, 0, tid);
    __pipeline_commit();
    ld_gemm_stage(smc + STAGE_BYTES, A, B, bm, bn, GBK, tid);
    __pipeline_commit();

    int buf_next = 2;
    for (int it = 0; it < NKIT; it++) {
        if (it + 2 < NKIT) {
            ld_gemm_stage(smc + buf_next * STAGE_BYTES, A, B, bm, bn, (it + 2) * GBK, tid);
            __pipeline_commit();
            __pipeline_wait_prior(2);
            buf_next = (buf_next + 1) % NSTAGE;
        } else if (it + 1 < NKIT) {
            __pipeline_wait_prior(1);
        } else {
            __pipeline_wait_prior(0);
        }
        __syncthreads();

        const uint32_t* sA = (const uint32_t*)(smc + (it % NSTAGE) * STAGE_BYTES);
        const uint32_t* sB = (const uint32_t*)(smc + (it % NSTAGE) * STAGE_BYTES + OPER_BYTES);

#pragma unroll
        for (int ks = 0; ks < 4; ks++) {
            const int k = ks * 8;
            uint32_t bfr[4][2];
#pragma unroll
            for (int ni = 0; ni < 4; ni++) {
                const int nb = no + ni * 8 + g;
                bfr[ni][0] = sB[nb * STRIDE + k + tg];
                bfr[ni][1] = sB[nb * STRIDE + k + tg + 4];
            }
#pragma unroll
            for (int mi = 0; mi < 4; mi++) {
                const int rb = mo + mi * 16 + g;
                uint32_t afr[4];
                afr[0] = sA[rb * STRIDE + k + tg];
                afr[1] = sA[(rb + 8) * STRIDE + k + tg];
                afr[2] = sA[rb * STRIDE + k + tg + 4];
                afr[3] = sA[(rb + 8) * STRIDE + k + tg + 4];
#pragma unroll
                for (int ni = 0; ni < 4; ni++)
                    mma_tf32(acc[mi][ni], afr, bfr[ni]);
            }
        }
        __syncthreads();
    }

    // epilogue
#pragma unroll
    for (int mi = 0; mi < 4; mi++) {
        const int m0 = bm + mo + mi * 16 + g;
#pragma unroll
        for (int ni = 0; ni < 4; ni++) {
            const int n = bn + no + ni * 8 + tg * 2;
            const float* c = acc[mi][ni];
            if (mode == 0) {
                const int which = n >> 10;
                const int cr = n & 1023;
                const int h = cr >> 6, d = cr & 63;
#pragma unroll
                for (int rr = 0; rr < 2; rr++) {
                    const int m = m0 + rr * 8;
                    const int b = m >> 12, t = m & 4095;
                    float v0 = c[rr * 2], v1 = c[rr * 2 + 1];
                    if (which == 0) { v0 *= 0.125f; v1 *= 0.125f; }
                    __nv_bfloat16 h0 = __float2bfloat16(v0);
                    __nv_bfloat16 h1 = __float2bfloat16(v1);
                    __nv_bfloat16 l0 = __float2bfloat16(v0 - __bfloat162float(h0));
                    __nv_bfloat16 l1 = __float2bfloat16(v1 - __bfloat162float(h1));
                    if (which < 2) {
                        const size_t off = ((size_t)(b * HEADS + h) * SEQ + t) * DH + d;
                        __nv_bfloat162 ph, pl;
                        ph.x = h0; ph.y = h1; pl.x = l0; pl.y = l1;
                        if (which == 0) {
                            *(__nv_bfloat162*)(g_qh + off) = ph;
                            *(__nv_bfloat162*)(g_ql + off) = pl;
                        } else {
                            *(__nv_bfloat162*)(g_kh + off) = ph;
                            *(__nv_bfloat162*)(g_kl + off) = pl;
                        }
                    } else {
                        // v transposed: [B,H,64,T]
                        const size_t off = ((size_t)(b * HEADS + h) * DH + d) * SEQ + t;
                        g_vth[off] = h0;       g_vth[off + SEQ] = h1;
                        g_vtl[off] = l0;       g_vtl[off + SEQ] = l1;
                    }
                }
            } else {
                const float2 bv = *(const float2*)(bias + n);
#pragma unroll
                for (int rr = 0; rr < 2; rr++) {
                    const int m = m0 + rr * 8;
                    *(float2*)(Y + (size_t)m * CDIM + n) =
                        make_float2(c[rr * 2] + bv.x, c[rr * 2 + 1] + bv.y);
                }
            }
        }
    }
}

// ---------------------------------------------------------------------------
// Stage 3: attention via mma.sync bf16 hi/lo split.
// Block = (b,h,chunk,qtile): 128 q x 512 keys. 256 threads, 8 warps x 16 rows.
// Key tiles of 128 processed as two 64-key halves (register pressure).
// ---------------------------------------------------------------------------
#define AQS 72     // K/Q smem row stride (bf16)
#define AVS 136    // Vt smem row stride (bf16)
#define ATT_SMEM (128*AQS*2*2 + 128*AQS*2*2 /*wrong-math guard, real below*/)
#undef ATT_SMEM
#define ATT_SMEM (2*(128*AQS*2) + 2*(128*AQS*2) + 2*(64*AVS*2) + 512*4)  // 110592

__device__ __forceinline__ void mma_bf16(float* c, const uint32_t* a,
                                         uint32_t b0, uint32_t b1) {
    asm volatile(
        "mma.sync.aligned.m16n8k16.row.col.f32.bf16.bf16.f32 "
        "{%0,%1,%2,%3}, {%4,%5,%6,%7}, {%8,%9}, {%0,%1,%2,%3};"
        : "+f"(c[0]), "+f"(c[1]), "+f"(c[2]), "+f"(c[3])
        : "r"(a[0]), "r"(a[1]), "r"(a[2]), "r"(a[3]), "r"(b0), "r"(b1));
}

__device__ __forceinline__ uint32_t pk2bf(float lo, float hi) {
    uint32_t r;
    asm("cvt.rn.bf16x2.f32 %0, %1, %2;" : "=r"(r) : "f"(hi), "f"(lo));
    return r;
}

__global__ __launch_bounds__(256, 2) void attn_mma() {
    extern __shared__ char smb[];
    __nv_bfloat16* sQh = (__nv_bfloat16*)smb;
    __nv_bfloat16* sQl = sQh + 128 * AQS;
    __nv_bfloat16* sKh = sQl + 128 * AQS;
    __nv_bfloat16* sKl = sKh + 128 * AQS;
    __nv_bfloat16* sVh = sKl + 128 * AQS;
    __nv_bfloat16* sVl = sVh + 64 * AVS;
    float* slam = (float*)(sVl + 64 * AVS);

    const int bx = blockIdx.x;
    const int qt = bx & 3;
    const int chunk = (bx >> 2) & 7;
    const int h = (bx >> 5) & 15;
    const int b = bx >> 9;
    const int tid = threadIdx.x;
    const int w = tid >> 5, lane = tid & 31;
    const int g = lane >> 2, tg = lane & 3;
    const int rw = w * 16;                 // warp's q-row base

    const size_t head = (size_t)(b * HEADS + h);
    const size_t qoff = (head * SEQ + chunk * CS + qt * QT) * DH;
    const size_t kbase_g = (head * SEQ + chunk * CS) * DH;
    const size_t vbase_g = head * DH * SEQ + (size_t)chunk * CS;  // [..][d][t]

    // lambda + Q (async)
    for (int j = tid; j < CS; j += 256) slam[j] = g_lam[h * SEQ + chunk * CS + j];
#pragma unroll
    for (int i = 0; i < 4; i++) {
        int idx = tid + i * 256;        // 0..1023
        int r = idx >> 3, c = idx & 7;
        __pipeline_memcpy_async(sQh + r * AQS + c * 8, g_qh + qoff + r * 64 + c * 8, 16);
        __pipeline_memcpy_async(sQl + r * AQS + c * 8, g_ql + qoff + r * 64 + c * 8, 16);
    }
    __pipeline_commit();

    float oacc[8][4];
#pragma unroll
    for (int d = 0; d < 8; d++)
#pragma unroll
        for (int e = 0; e < 4; e++) oacc[d][e] = 0.0f;
    float m0 = -1e30f, m1 = -1e30f, l0 = 0.0f, l1 = 0.0f;

    const uint32_t* q32h = (const uint32_t*)sQh;
    const uint32_t* q32l = (const uint32_t*)sQl;
    const uint32_t* k32h = (const uint32_t*)sKh;
    const uint32_t* k32l = (const uint32_t*)sKl;
    const uint32_t* v32h = (const uint32_t*)sVh;
    const uint32_t* v32l = (const uint32_t*)sVl;

    for (int kt = 0; kt < 4; kt++) {
        __syncthreads();   // prev compute done; smem reusable
#pragma unroll
        for (int i = 0; i < 4; i++) {
            int idx = tid + i * 256;
            int r = idx >> 3, c = idx & 7;
            size_t src = kbase_g + (size_t)(kt * 128 + r) * 64 + c * 8;
            __pipeline_memcpy_async(sKh + r * AQS + c * 8, g_kh + src, 16);
            __pipeline_memcpy_async(sKl + r * AQS + c * 8, g_kl + src, 16);
        }
#pragma unroll
        for (int i = 0; i < 4; i++) {
            int idx = tid + i * 256;
            int r = idx >> 4, c = idx & 15;    // r: dh row 0..63, c: key chunk
            size_t src = vbase_g + (size_t)r * SEQ + kt * 128 + c * 8;
            __pipeline_memcpy_async(sVh + r * AVS + c * 8, g_vth + src, 16);
            __pipeline_memcpy_async(sVl + r * AVS + c * 8, g_vtl + src, 16);
        }
        __pipeline_commit();
        __pipeline_wait_prior(0);
        __syncthreads();

#pragma unroll
        for (int hh = 0; hh < 2; hh++) {
            const int kb = hh * 64;            // key offset within the 128-tile

            // ---- S = Q K^T (bf16 split, fp32 accum) ----
            float sacc[8][4];
#pragma unroll
            for (int j = 0; j < 8; j++)
#pragma unroll
                for (int e = 0; e < 4; e++) sacc[j][e] = 0.0f;

#pragma unroll
            for (int ks = 0; ks < 4; ks++) {
                const int ko = ks * 16 + 2 * tg;
                uint32_t ah[4], al[4];
                ah[0] = q32h[((rw + g) * AQS + ko) >> 1];
                ah[1] = q32h[((rw + g + 8) * AQS + ko) >> 1];
                ah[2] = q32h[((rw + g) * AQS + ko + 8) >> 1];
                ah[3] = q32h[((rw + g + 8) * AQS + ko + 8) >> 1];
                al[0] = q32l[((rw + g) * AQS + ko) >> 1];
                al[1] = q32l[((rw + g + 8) * AQS + ko) >> 1];
                al[2] = q32l[((rw + g) * AQS + ko + 8) >> 1];
                al[3] = q32l[((rw + g + 8) * AQS + ko + 8) >> 1];
#pragma unroll
                for (int j = 0; j < 8; j++) {
                    const int kr = (kb + j * 8 + g) * AQS + ko;
                    uint32_t bh0 = k32h[kr >> 1];
                    uint32_t bh1 = k32h[(kr + 8) >> 1];
                    uint32_t bl0 = k32l[kr >> 1];
                    uint32_t bl1 = k32l[(kr + 8) >> 1];
                    mma_bf16(sacc[j], ah, bh0, bh1);
                    mma_bf16(sacc[j], ah, bl0, bl1);
                    mma_bf16(sacc[j], al, bh0, bh1);
                }
            }

            // ---- gate + online softmax ----
            float ml0 = -1e30f, ml1 = -1e30f;
#pragma unroll
            for (int j = 0; j < 8; j++) {
                float2 la = *(float2*)&slam[kt * 128 + kb + j * 8 + 2 * tg];
                sacc[j][0] *= la.x; sacc[j][1] *= la.y;
                sacc[j][2] *= la.x; sacc[j][3] *= la.y;
                ml0 = fmaxf(ml0, fmaxf(sacc[j][0], sacc[j][1]));
                ml1 = fmaxf(ml1, fmaxf(sacc[j][2], sacc[j][3]));
            }
#pragma unroll
            for (int s = 1; s < 4; s <<= 1) {
                ml0 = fmaxf(ml0, __shfl_xor_sync(0xffffffffu, ml0, s));
                ml1 = fmaxf(ml1, __shfl_xor_sync(0xffffffffu, ml1, s));
            }
            const float mn0 = fmaxf(m0, ml0);
            const float mn1 = fmaxf(m1, ml1);
            const float cr0 = __expf(m0 - mn0);
            const float cr1 = __expf(m1 - mn1);
            float rs0 = 0.0f, rs1 = 0.0f;
#pragma unroll
            for (int j = 0; j < 8; j++) {
                sacc[j][0] = __expf(sacc[j][0] - mn0);
                sacc[j][1] = __expf(sacc[j][1] - mn0);
                sacc[j][2] = __expf(sacc[j][2] - mn1);
                sacc[j][3] = __expf(sacc[j][3] - mn1);
                rs0 += sacc[j][0] + sacc[j][1];
                rs1 += sacc[j][2] + sacc[j][3];
            }
#pragma unroll
            for (int s = 1; s < 4; s <<= 1) {
                rs0 += __shfl_xor_sync(0xffffffffu, rs0, s);
                rs1 += __shfl_xor_sync(0xffffffffu, rs1, s);
            }
            l0 = l0 * cr0 + rs0;  m0 = mn0;
            l1 = l1 * cr1 + rs1;  m1 = mn1;
#pragma unroll
            for (int d = 0; d < 8; d++) {
                oacc[d][0] *= cr0; oacc[d][1] *= cr0;
                oacc[d][2] *= cr1; oacc[d][3] *= cr1;
            }

            // ---- O += P V (bf16 split) ----
#pragma unroll
            for (int kp = 0; kp < 4; kp++) {
                uint32_t ph[4], pl[4];
#pragma unroll
                for (int u = 0; u < 2; u++) {         // u=0: j=2kp (k0..7), u=1: j=2kp+1 (k8..15)
                    const float* p = sacc[2 * kp + u];
                    float h0f = __bfloat162float(__float2bfloat16(p[0]));
                    float h1f = __bfloat162float(__float2bfloat16(p[1]));
                    float h2f = __bfloat162float(__float2bfloat16(p[2]));
                    float h3f = __bfloat162float(__float2bfloat16(p[3]));
                    ph[0 + 2 * u] = pk2bf(h0f, h1f);
                    ph[1 + 2 * u] = pk2bf(h2f, h3f);
                    pl[0 + 2 * u] = pk2bf(p[0] - h0f, p[1] - h1f);
                    pl[1 + 2 * u] = pk2bf(p[2] - h2f, p[3] - h3f);
                }
                // reorder to A-frag: a0=(row g,k0..7)=ph[0], a1=(g+8,k0..7)=ph[1],
                //                    a2=(row g,k8..15)=ph[2], a3=(g+8,k8..15)=ph[3]  ✓
#pragma unroll
                for (int d = 0; d < 8; d++) {
                    const int vr = (d * 8 + g) * AVS + kb + kp * 16 + 2 * tg;
                    uint32_t bh0 = v32h[vr >> 1];
                    uint32_t bh1 = v32h[(vr + 8) >> 1];
                    uint32_t bl0 = v32l[vr >> 1];
                    uint32_t bl1 = v32l[(vr + 8) >> 1];
                    mma_bf16(oacc[d], ph, bh0, bh1);
                    mma_bf16(oacc[d], ph, bl0, bl1);
                    mma_bf16(oacc[d], pl, bh0, bh1);
                }
            }
        }
    }

    // ---- epilogue: normalize, tf32-round, store ----
    const float inv0 = 1.0f / l0, inv1 = 1.0f / l1;
    const int t0 = chunk * CS + qt * QT + rw;
    const size_t row0 = ((size_t)b * SEQ + t0 + g) * CDIM + h * DH;
    const size_t row1 = row0 + (size_t)8 * CDIM;
#pragma unroll
    for (int d = 0; d < 8; d++) {
        uint2 o0, o1;
        float a = oacc[d][0] * inv0, bb = oacc[d][1] * inv0;
        float c = oacc[d][2] * inv1, dd = oacc[d][3] * inv1;
        asm("cvt.rna.tf32.f32 %0, %1;" : "=r"(o0.x) : "f"(a));
        asm("cvt.rna.tf32.f32 %0, %1;" : "=r"(o0.y) : "f"(bb));
        asm("cvt.rna.tf32.f32 %0, %1;" : "=r"(o1.x) : "f"(c));
        asm("cvt.rna.tf32.f32 %0, %1;" : "=r"(o1.y) : "f"(dd));
        *(uint2*)(g_attn + row0 + d * 8 + 2 * tg) = o0;
        *(uint2*)(g_attn + row1 + d * 8 + 2 * tg) = o1;
    }
}

// ---------------------------------------------------------------------------
// Launcher
// ---------------------------------------------------------------------------
extern "C" void kernel_launch(void* const* d_in, const int* in_sizes, int n_in,
                              void* d_out, int out_size) {
    const float* x    = (const float*)d_in[0];
    const float* Wqkv = (const float*)d_in[1];
    const float* Wout = (const float*)d_in[2];
    const float* bout = (const float*)d_in[3];
    const float* Wl1  = (const float*)d_in[4];
    const float* bl1  = (const float*)d_in[5];
    const float* Wl2  = (const float*)d_in[6];
    const float* bl2  = (const float*)d_in[7];
    float* out = (float*)d_out;

    cudaFuncSetAttribute(attn_mma, cudaFuncAttributeMaxDynamicSharedMemorySize, ATT_SMEM);
    cudaFuncSetAttribute(gemm_mma, cudaFuncAttributeMaxDynamicSharedMemorySize, GEMM_SMEM);

    float *x32, *w32, *o32, *a32;
    cudaGetSymbolAddress((void**)&x32, g_x32);
    cudaGetSymbolAddress((void**)&w32, g_wqkv32);
    cudaGetSymbolAddress((void**)&o32, g_wout32);
    cudaGetSymbolAddress((void**)&a32, g_attn);

    lam_kernel<<<SEQ / 256, 256>>>(Wl1, bl1, Wl2, bl2);

    {
        int n4 = M_TOT * CDIM / 4;
        round_tf32<<<(n4 + 255) / 256, 256>>>((const float4*)x, (uint4*)x32, n4);
        n4 = 3 * CDIM * CDIM / 4;
        round_tf32<<<(n4 + 255) / 256, 256>>>((const float4*)Wqkv, (uint4*)w32, n4);
        n4 = CDIM * CDIM / 4;
        round_tf32<<<(n4 + 255) / 256, 256>>>((const float4*)Wout, (uint4*)o32, n4);
    }

    gemm_mma<<<dim3(3 * CDIM / GBN, M_TOT / GBM), 256, GEMM_SMEM>>>(
        x32, w32, nullptr, nullptr, 0);

    attn_mma<<<BATCH * HEADS * 8 * (CS / QT), 256, ATT_SMEM>>>();

    gemm_mma<<<dim3(CDIM / GBN, M_TOT / GBM), 256, GEMM_SMEM>>>(
        a32, o32, bout, out, 1);
}

// round 6
// speedup vs baseline: 4.5535x; 1.3717x over previous
#include <cuda_runtime.h>
#include <cuda_bf16.h>
#include <cuda_fp16.h>
#include <cuda_pipeline.h>
#include <math.h>
#include <cstdint>

// ============================================================================
// LogLinearAttention  (B=4, T=4096, C=1024, H=16, dh=64, nc=8, cs=512)
// R6: dense GEMMs moved from tf32 m16n8k8 to fp16 m16n8k16 (same 11-bit
//     significand -> identical error statistics, 2x FLOPs/instr, half the
//     LDS + DRAM traffic). Attention unchanged (bf16 hi/lo split mma).
// ============================================================================

#define BATCH 4
#define SEQ   4096
#define CDIM  1024
#define HEADS 16
#define DH    64
#define CS    512
#define QT    128
#define M_TOT (BATCH * SEQ)

__device__ float g_lam[HEADS * SEQ];
__device__ __half g_x16[(size_t)M_TOT * CDIM];
__device__ __half g_w16[(size_t)3 * CDIM * CDIM];
__device__ __half g_wo16[(size_t)CDIM * CDIM];
__device__ __half g_a16[(size_t)M_TOT * CDIM];      // attention output, fp16

// bf16 hi/lo tensors for attention
#define QKV_ELEMS ((size_t)BATCH * HEADS * SEQ * DH)
__device__ __nv_bfloat16 g_qh[QKV_ELEMS];
__device__ __nv_bfloat16 g_ql[QKV_ELEMS];
__device__ __nv_bfloat16 g_kh[QKV_ELEMS];
__device__ __nv_bfloat16 g_kl[QKV_ELEMS];
__device__ __nv_bfloat16 g_vth[QKV_ELEMS];          // [B,H,64,T] transposed
__device__ __nv_bfloat16 g_vtl[QKV_ELEMS];

// ---------------------------------------------------------------------------
// fp32 -> fp16 conversion prepass
// ---------------------------------------------------------------------------
__global__ void conv_f16(const float4* __restrict__ src, __half2* __restrict__ dst, int n4) {
    int i = blockIdx.x * 256 + threadIdx.x;
    if (i >= n4) return;
    float4 v = src[i];
    dst[2 * i]     = __floats2half2_rn(v.x, v.y);
    dst[2 * i + 1] = __floats2half2_rn(v.z, v.w);
}

// ---------------------------------------------------------------------------
// Stage 1: lambda gates
// ---------------------------------------------------------------------------
__global__ void lam_kernel(const float* __restrict__ Wl1, const float* __restrict__ bl1,
                           const float* __restrict__ Wl2, const float* __restrict__ bl2) {
    int t = blockIdx.x * blockDim.x + threadIdx.x;
    if (t >= SEQ) return;
    float lp = logf((float)t + 1.0f);
    float h1[64];
#pragma unroll
    for (int u = 0; u < 64; u++) {
        float v = lp * Wl1[u] + bl1[u];
        h1[u] = v > 0.0f ? v : 0.0f;
    }
#pragma unroll
    for (int h = 0; h < HEADS; h++) {
        float s = bl2[h];
#pragma unroll
        for (int u = 0; u < 64; u++) s += h1[u] * Wl2[h * 64 + u];
        g_lam[h * SEQ + t] = 1.0f / (1.0f + expf(-s));
    }
}

// ---------------------------------------------------------------------------
// FP16 mma.sync GEMM.  C[m,n] = sum_k A[m,k]*B[n,k], fp32 accumulate.
// Tile 128x128x32, 256 threads (8 warps 2x4), warp tile 64x32 = 4x4 m16n8,
// two k16 steps per K-iter. 3-stage cp.async.
// mode 0: qkv epilogue (bf16 hi/lo q,k + transposed v).  mode 1: +bias -> Y.
// ---------------------------------------------------------------------------
#define GBM 128
#define GBN 128
#define GBK 32
#define HSTRIDE 40                        // halfs per smem row (32 + 8 pad)
#define OPER_HB (128 * HSTRIDE * 2)       // 10240 bytes per operand
#define STAGE_B (2 * OPER_HB)             // 20480
#define NSTAGE 3
#define GEMM_SMEM (NSTAGE * STAGE_B)      // 61440
#define NKIT (CDIM / GBK)                 // 32

__device__ __forceinline__ void mma_f16(float* c, const uint32_t* a,
                                        uint32_t b0, uint32_t b1) {
    asm volatile(
        "mma.sync.aligned.m16n8k16.row.col.f32.f16.f16.f32 "
        "{%0,%1,%2,%3}, {%4,%5,%6,%7}, {%8,%9}, {%0,%1,%2,%3};"
        : "+f"(c[0]), "+f"(c[1]), "+f"(c[2]), "+f"(c[3])
        : "r"(a[0]), "r"(a[1]), "r"(a[2]), "r"(a[3]), "r"(b0), "r"(b1));
}

__device__ __forceinline__ void ld_gemm16(char* st, const __half* __restrict__ A,
                                          const __half* __restrict__ B,
                                          int bm, int bn, int k0, int tid) {
#pragma unroll
    for (int i = 0; i < 2; i++) {
        int idx = tid + i * 256;          // 0..511
        int row = idx >> 2;               // 0..127
        int c4  = idx & 3;                // 16B chunk (8 halfs)
        __pipeline_memcpy_async(st + (row * HSTRIDE + c4 * 8) * 2,
                                A + (size_t)(bm + row) * CDIM + k0 + c4 * 8, 16);
        __pipeline_memcpy_async(st + OPER_HB + (row * HSTRIDE + c4 * 8) * 2,
                                B + (size_t)(bn + row) * CDIM + k0 + c4 * 8, 16);
    }
}

__device__ __forceinline__ uint32_t pk2bf(float lo, float hi) {
    uint32_t r;
    asm("cvt.rn.bf16x2.f32 %0, %1, %2;" : "=r"(r) : "f"(hi), "f"(lo));
    return r;
}

__global__ __launch_bounds__(256, 2) void gemm_f16(const __half* __restrict__ A,
                                                   const __half* __restrict__ B,
                                                   const float* __restrict__ bias,
                                                   float* __restrict__ Y, int mode) {
    extern __shared__ char smc[];
    const int tid = threadIdx.x;
    const int w = tid >> 5, lane = tid & 31;
    const int g = lane >> 2, tg = lane & 3;
    const int mo = (w >> 2) * 64;
    const int no = (w & 3) * 32;
    const int bm = blockIdx.y * GBM;
    const int bn = blockIdx.x * GBN;

    float acc[4][4][4];
#pragma unroll
    for (int mi = 0; mi < 4; mi++)
#pragma unroll
        for (int ni = 0; ni < 4; ni++)
#pragma unroll
            for (int e = 0; e < 4; e++) acc[mi][ni][e] = 0.0f;

    ld_gemm16(smc, A, B, bm, bn, 0, tid);
    __pipeline_commit();
    ld_gemm16(smc + STAGE_B, A, B, bm, bn, GBK, tid);
    __pipeline_commit();

    int buf_next = 2;
    for (int it = 0; it < NKIT; it++) {
        if (it + 2 < NKIT) {
            ld_gemm16(smc + buf_next * STAGE_B, A, B, bm, bn, (it + 2) * GBK, tid);
            __pipeline_commit();
            __pipeline_wait_prior(2);
            buf_next = (buf_next + 1) % NSTAGE;
        } else if (it + 1 < NKIT) {
            __pipeline_wait_prior(1);
        } else {
            __pipeline_wait_prior(0);
        }
        __syncthreads();

        const uint32_t* sA = (const uint32_t*)(smc + (it % NSTAGE) * STAGE_B);
        const uint32_t* sB = (const uint32_t*)(smc + (it % NSTAGE) * STAGE_B + OPER_HB);

#pragma unroll
        for (int ks = 0; ks < 2; ks++) {
            const int kc = ks * 8 + tg;          // uint32 column (HSTRIDE/2 = 20)
            uint32_t bfr[4][2];
#pragma unroll
            for (int ni = 0; ni < 4; ni++) {
                const int nb = no + ni * 8 + g;
                bfr[ni][0] = sB[nb * 20 + kc];
                bfr[ni][1] = sB[nb * 20 + kc + 4];
            }
#pragma unroll
            for (int mi = 0; mi < 4; mi++) {
                const int rb = mo + mi * 16 + g;
                uint32_t afr[4];
                afr[0] = sA[rb * 20 + kc];
                afr[1] = sA[(rb + 8) * 20 + kc];
                afr[2] = sA[rb * 20 + kc + 4];
                afr[3] = sA[(rb + 8) * 20 + kc + 4];
#pragma unroll
                for (int ni = 0; ni < 4; ni++)
                    mma_f16(acc[mi][ni], afr, bfr[ni][0], bfr[ni][1]);
            }
        }
        __syncthreads();
    }

    // epilogue
#pragma unroll
    for (int mi = 0; mi < 4; mi++) {
        const int m0 = bm + mo + mi * 16 + g;
#pragma unroll
        for (int ni = 0; ni < 4; ni++) {
            const int n = bn + no + ni * 8 + tg * 2;
            const float* c = acc[mi][ni];
            if (mode == 0) {
                const int which = n >> 10;
                const int cr = n & 1023;
                const int h = cr >> 6, d = cr & 63;
#pragma unroll
                for (int rr = 0; rr < 2; rr++) {
                    const int m = m0 + rr * 8;
                    const int b = m >> 12, t = m & 4095;
                    float v0 = c[rr * 2], v1 = c[rr * 2 + 1];
                    if (which == 0) { v0 *= 0.125f; v1 *= 0.125f; }
                    __nv_bfloat16 h0 = __float2bfloat16(v0);
                    __nv_bfloat16 h1 = __float2bfloat16(v1);
                    __nv_bfloat16 l0 = __float2bfloat16(v0 - __bfloat162float(h0));
                    __nv_bfloat16 l1 = __float2bfloat16(v1 - __bfloat162float(h1));
                    if (which < 2) {
                        const size_t off = ((size_t)(b * HEADS + h) * SEQ + t) * DH + d;
                        __nv_bfloat162 ph, pl;
                        ph.x = h0; ph.y = h1; pl.x = l0; pl.y = l1;
                        if (which == 0) {
                            *(__nv_bfloat162*)(g_qh + off) = ph;
                            *(__nv_bfloat162*)(g_ql + off) = pl;
                        } else {
                            *(__nv_bfloat162*)(g_kh + off) = ph;
                            *(__nv_bfloat162*)(g_kl + off) = pl;
                        }
                    } else {
                        const size_t off = ((size_t)(b * HEADS + h) * DH + d) * SEQ + t;
                        g_vth[off] = h0;       g_vth[off + SEQ] = h1;
                        g_vtl[off] = l0;       g_vtl[off + SEQ] = l1;
                    }
                }
            } else {
                const float2 bv = *(const float2*)(bias + n);
#pragma unroll
                for (int rr = 0; rr < 2; rr++) {
                    const int m = m0 + rr * 8;
                    *(float2*)(Y + (size_t)m * CDIM + n) =
                        make_float2(c[rr * 2] + bv.x, c[rr * 2 + 1] + bv.y);
                }
            }
        }
    }
}

// ---------------------------------------------------------------------------
// Stage 3: attention via mma.sync bf16 hi/lo split (unchanged from R5 except
// fp16 epilogue for the out-GEMM input).
// ---------------------------------------------------------------------------
#define AQS 72
#define AVS 136
#define ATT_SMEM (2*(128*AQS*2) + 2*(128*AQS*2) + 2*(64*AVS*2) + 512*4)

__device__ __forceinline__ void mma_bf16(float* c, const uint32_t* a,
                                         uint32_t b0, uint32_t b1) {
    asm volatile(
        "mma.sync.aligned.m16n8k16.row.col.f32.bf16.bf16.f32 "
        "{%0,%1,%2,%3}, {%4,%5,%6,%7}, {%8,%9}, {%0,%1,%2,%3};"
        : "+f"(c[0]), "+f"(c[1]), "+f"(c[2]), "+f"(c[3])
        : "r"(a[0]), "r"(a[1]), "r"(a[2]), "r"(a[3]), "r"(b0), "r"(b1));
}

__global__ __launch_bounds__(256, 2) void attn_mma() {
    extern __shared__ char smb[];
    __nv_bfloat16* sQh = (__nv_bfloat16*)smb;
    __nv_bfloat16* sQl = sQh + 128 * AQS;
    __nv_bfloat16* sKh = sQl + 128 * AQS;
    __nv_bfloat16* sKl = sKh + 128 * AQS;
    __nv_bfloat16* sVh = sKl + 128 * AQS;
    __nv_bfloat16* sVl = sVh + 64 * AVS;
    float* slam = (float*)(sVl + 64 * AVS);

    const int bx = blockIdx.x;
    const int qt = bx & 3;
    const int chunk = (bx >> 2) & 7;
    const int h = (bx >> 5) & 15;
    const int b = bx >> 9;
    const int tid = threadIdx.x;
    const int w = tid >> 5, lane = tid & 31;
    const int g = lane >> 2, tg = lane & 3;
    const int rw = w * 16;

    const size_t head = (size_t)(b * HEADS + h);
    const size_t qoff = (head * SEQ + chunk * CS + qt * QT) * DH;
    const size_t kbase_g = (head * SEQ + chunk * CS) * DH;
    const size_t vbase_g = head * DH * SEQ + (size_t)chunk * CS;

    for (int j = tid; j < CS; j += 256) slam[j] = g_lam[h * SEQ + chunk * CS + j];
#pragma unroll
    for (int i = 0; i < 4; i++) {
        int idx = tid + i * 256;
        int r = idx >> 3, c = idx & 7;
        __pipeline_memcpy_async(sQh + r * AQS + c * 8, g_qh + qoff + r * 64 + c * 8, 16);
        __pipeline_memcpy_async(sQl + r * AQS + c * 8, g_ql + qoff + r * 64 + c * 8, 16);
    }
    __pipeline_commit();

    float oacc[8][4];
#pragma unroll
    for (int d = 0; d < 8; d++)
#pragma unroll
        for (int e = 0; e < 4; e++) oacc[d][e] = 0.0f;
    float m0 = -1e30f, m1 = -1e30f, l0 = 0.0f, l1 = 0.0f;

    const uint32_t* q32h = (const uint32_t*)sQh;
    const uint32_t* q32l = (const uint32_t*)sQl;
    const uint32_t* k32h = (const uint32_t*)sKh;
    const uint32_t* k32l = (const uint32_t*)sKl;
    const uint32_t* v32h = (const uint32_t*)sVh;
    const uint32_t* v32l = (const uint32_t*)sVl;

    for (int kt = 0; kt < 4; kt++) {
        __syncthreads();
#pragma unroll
        for (int i = 0; i < 4; i++) {
            int idx = tid + i * 256;
            int r = idx >> 3, c = idx & 7;
            size_t src = kbase_g + (size_t)(kt * 128 + r) * 64 + c * 8;
            __pipeline_memcpy_async(sKh + r * AQS + c * 8, g_kh + src, 16);
            __pipeline_memcpy_async(sKl + r * AQS + c * 8, g_kl + src, 16);
        }
#pragma unroll
        for (int i = 0; i < 4; i++) {
            int idx = tid + i * 256;
            int r = idx >> 4, c = idx & 15;
            size_t src = vbase_g + (size_t)r * SEQ + kt * 128 + c * 8;
            __pipeline_memcpy_async(sVh + r * AVS + c * 8, g_vth + src, 16);
            __pipeline_memcpy_async(sVl + r * AVS + c * 8, g_vtl + src, 16);
        }
        __pipeline_commit();
        __pipeline_wait_prior(0);
        __syncthreads();

#pragma unroll
        for (int hh = 0; hh < 2; hh++) {
            const int kb = hh * 64;

            float sacc[8][4];
#pragma unroll
            for (int j = 0; j < 8; j++)
#pragma unroll
                for (int e = 0; e < 4; e++) sacc[j][e] = 0.0f;

#pragma unroll
            for (int ks = 0; ks < 4; ks++) {
                const int ko = ks * 16 + 2 * tg;
                uint32_t ah[4], al[4];
                ah[0] = q32h[((rw + g) * AQS + ko) >> 1];
                ah[1] = q32h[((rw + g + 8) * AQS + ko) >> 1];
                ah[2] = q32h[((rw + g) * AQS + ko + 8) >> 1];
                ah[3] = q32h[((rw + g + 8) * AQS + ko + 8) >> 1];
                al[0] = q32l[((rw + g) * AQS + ko) >> 1];
                al[1] = q32l[((rw + g + 8) * AQS + ko) >> 1];
                al[2] = q32l[((rw + g) * AQS + ko + 8) >> 1];
                al[3] = q32l[((rw + g + 8) * AQS + ko + 8) >> 1];
#pragma unroll
                for (int j = 0; j < 8; j++) {
                    const int kr = (kb + j * 8 + g) * AQS + ko;
                    uint32_t bh0 = k32h[kr >> 1];
                    uint32_t bh1 = k32h[(kr + 8) >> 1];
                    uint32_t bl0 = k32l[kr >> 1];
                    uint32_t bl1 = k32l[(kr + 8) >> 1];
                    mma_bf16(sacc[j], ah, bh0, bh1);
                    mma_bf16(sacc[j], ah, bl0, bl1);
                    mma_bf16(sacc[j], al, bh0, bh1);
                }
            }

            float ml0 = -1e30f, ml1 = -1e30f;
#pragma unroll
            for (int j = 0; j < 8; j++) {
                float2 la = *(float2*)&slam[kt * 128 + kb + j * 8 + 2 * tg];
                sacc[j][0] *= la.x; sacc[j][1] *= la.y;
                sacc[j][2] *= la.x; sacc[j][3] *= la.y;
                ml0 = fmaxf(ml0, fmaxf(sacc[j][0], sacc[j][1]));
                ml1 = fmaxf(ml1, fmaxf(sacc[j][2], sacc[j][3]));
            }
#pragma unroll
            for (int s = 1; s < 4; s <<= 1) {
                ml0 = fmaxf(ml0, __shfl_xor_sync(0xffffffffu, ml0, s));
                ml1 = fmaxf(ml1, __shfl_xor_sync(0xffffffffu, ml1, s));
            }
            const float mn0 = fmaxf(m0, ml0);
            const float mn1 = fmaxf(m1, ml1);
            const float cr0 = __expf(m0 - mn0);
            const float cr1 = __expf(m1 - mn1);
            float rs0 = 0.0f, rs1 = 0.0f;
#pragma unroll
            for (int j = 0; j < 8; j++) {
                sacc[j][0] = __expf(sacc[j][0] - mn0);
                sacc[j][1] = __expf(sacc[j][1] - mn0);
                sacc[j][2] = __expf(sacc[j][2] - mn1);
                sacc[j][3] = __expf(sacc[j][3] - mn1);
                rs0 += sacc[j][0] + sacc[j][1];
                rs1 += sacc[j][2] + sacc[j][3];
            }
#pragma unroll
            for (int s = 1; s < 4; s <<= 1) {
                rs0 += __shfl_xor_sync(0xffffffffu, rs0, s);
                rs1 += __shfl_xor_sync(0xffffffffu, rs1, s);
            }
            l0 = l0 * cr0 + rs0;  m0 = mn0;
            l1 = l1 * cr1 + rs1;  m1 = mn1;
#pragma unroll
            for (int d = 0; d < 8; d++) {
                oacc[d][0] *= cr0; oacc[d][1] *= cr0;
                oacc[d][2] *= cr1; oacc[d][3] *= cr1;
            }

#pragma unroll
            for (int kp = 0; kp < 4; kp++) {
                uint32_t ph[4], pl[4];
#pragma unroll
                for (int u = 0; u < 2; u++) {
                    const float* p = sacc[2 * kp + u];
                    float h0f = __bfloat162float(__float2bfloat16(p[0]));
                    float h1f = __bfloat162float(__float2bfloat16(p[1]));
                    float h2f = __bfloat162float(__float2bfloat16(p[2]));
                    float h3f = __bfloat162float(__float2bfloat16(p[3]));
                    ph[0 + 2 * u] = pk2bf(h0f, h1f);
                    ph[1 + 2 * u] = pk2bf(h2f, h3f);
                    pl[0 + 2 * u] = pk2bf(p[0] - h0f, p[1] - h1f);
                    pl[1 + 2 * u] = pk2bf(p[2] - h2f, p[3] - h3f);
                }
#pragma unroll
                for (int d = 0; d < 8; d++) {
                    const int vr = (d * 8 + g) * AVS + kb + kp * 16 + 2 * tg;
                    uint32_t bh0 = v32h[vr >> 1];
                    uint32_t bh1 = v32h[(vr + 8) >> 1];
                    uint32_t bl0 = v32l[vr >> 1];
                    uint32_t bl1 = v32l[(vr + 8) >> 1];
                    mma_bf16(oacc[d], ph, bh0, bh1);
                    mma_bf16(oacc[d], ph, bl0, bl1);
                    mma_bf16(oacc[d], pl, bh0, bh1);
                }
            }
        }
    }

    // epilogue: normalize, write fp16 for the out GEMM
    const float inv0 = 1.0f / l0, inv1 = 1.0f / l1;
    const int t0 = chunk * CS + qt * QT + rw;
    const size_t row0 = ((size_t)b * SEQ + t0 + g) * CDIM + h * DH;
    const size_t row1 = row0 + (size_t)8 * CDIM;
#pragma unroll
    for (int d = 0; d < 8; d++) {
        *(__half2*)(g_a16 + row0 + d * 8 + 2 * tg) =
            __floats2half2_rn(oacc[d][0] * inv0, oacc[d][1] * inv0);
        *(__half2*)(g_a16 + row1 + d * 8 + 2 * tg) =
            __floats2half2_rn(oacc[d][2] * inv1, oacc[d][3] * inv1);
    }
}

// ---------------------------------------------------------------------------
// Launcher
// ---------------------------------------------------------------------------
extern "C" void kernel_launch(void* const* d_in, const int* in_sizes, int n_in,
                              void* d_out, int out_size) {
    const float* x    = (const float*)d_in[0];
    const float* Wqkv = (const float*)d_in[1];
    const float* Wout = (const float*)d_in[2];
    const float* bout = (const float*)d_in[3];
    const float* Wl1  = (const float*)d_in[4];
    const float* bl1  = (const float*)d_in[5];
    const float* Wl2  = (const float*)d_in[6];
    const float* bl2  = (const float*)d_in[7];
    float* out = (float*)d_out;

    cudaFuncSetAttribute(attn_mma, cudaFuncAttributeMaxDynamicSharedMemorySize, ATT_SMEM);
    cudaFuncSetAttribute(gemm_f16, cudaFuncAttributeMaxDynamicSharedMemorySize, GEMM_SMEM);

    __half *x16, *w16, *wo16, *a16;
    cudaGetSymbolAddress((void**)&x16, g_x16);
    cudaGetSymbolAddress((void**)&w16, g_w16);
    cudaGetSymbolAddress((void**)&wo16, g_wo16);
    cudaGetSymbolAddress((void**)&a16, g_a16);

    lam_kernel<<<SEQ / 256, 256>>>(Wl1, bl1, Wl2, bl2);

    {
        int n4 = M_TOT * CDIM / 4;
        conv_f16<<<(n4 + 255) / 256, 256>>>((const float4*)x, (__half2*)x16, n4);
        n4 = 3 * CDIM * CDIM / 4;
        conv_f16<<<(n4 + 255) / 256, 256>>>((const float4*)Wqkv, (__half2*)w16, n4);
        n4 = CDIM * CDIM / 4;
        conv_f16<<<(n4 + 255) / 256, 256>>>((const float4*)Wout, (__half2*)wo16, n4);
    }

    gemm_f16<<<dim3(3 * CDIM / GBN, M_TOT / GBM), 256, GEMM_SMEM>>>(
        x16, w16, nullptr, nullptr, 0);

    attn_mma<<<BATCH * HEADS * 8 * (CS / QT), 256, ATT_SMEM>>>();

    gemm_f16<<<dim3(CDIM / GBN, M_TOT / GBM), 256, GEMM_SMEM>>>(
        a16, wo16, bout, out, 1);
}

// round 7
// speedup vs baseline: 5.0001x; 1.0981x over previous
#include <cuda_runtime.h>
#include <cuda_bf16.h>
#include <cuda_fp16.h>
#include <cuda_pipeline.h>
#include <math.h>
#include <cstdint>

// ============================================================================
// LogLinearAttention  (B=4, T=4096, C=1024, H=16, dh=64, nc=8, cs=512)
// R7: ldmatrix.m8n8.x4 fragment loads everywhere (GEMM A/B, attention Q/K/V)
//     -> 4x fewer shared-load issues in the MMA hot loops. Math unchanged:
//     fp16 m16n8k16 GEMMs, bf16 hi/lo split attention.
// ============================================================================

#define BATCH 4
#define SEQ   4096
#define CDIM  1024
#define HEADS 16
#define DH    64
#define CS    512
#define QT    128
#define M_TOT (BATCH * SEQ)

__device__ float g_lam[HEADS * SEQ];
__device__ __half g_x16[(size_t)M_TOT * CDIM];
__device__ __half g_w16[(size_t)3 * CDIM * CDIM];
__device__ __half g_wo16[(size_t)CDIM * CDIM];
__device__ __half g_a16[(size_t)M_TOT * CDIM];

#define QKV_ELEMS ((size_t)BATCH * HEADS * SEQ * DH)
__device__ __nv_bfloat16 g_qh[QKV_ELEMS];
__device__ __nv_bfloat16 g_ql[QKV_ELEMS];
__device__ __nv_bfloat16 g_kh[QKV_ELEMS];
__device__ __nv_bfloat16 g_kl[QKV_ELEMS];
__device__ __nv_bfloat16 g_vth[QKV_ELEMS];
__device__ __nv_bfloat16 g_vtl[QKV_ELEMS];

// ---------------------------------------------------------------------------
__device__ __forceinline__ uint32_t smem_u32(const void* p) {
    uint32_t a;
    asm("{ .reg .u64 t; cvta.to.shared.u64 t, %1; cvt.u32.u64 %0, t; }" : "=r"(a) : "l"(p));
    return a;
}
__device__ __forceinline__ void ldm_x4(uint32_t& r0, uint32_t& r1, uint32_t& r2,
                                       uint32_t& r3, uint32_t addr) {
    asm volatile("ldmatrix.sync.aligned.m8n8.x4.shared.b16 {%0,%1,%2,%3}, [%4];"
                 : "=r"(r0), "=r"(r1), "=r"(r2), "=r"(r3) : "r"(addr));
}
__device__ __forceinline__ uint32_t pk2bf(float lo, float hi) {
    uint32_t r;
    asm("cvt.rn.bf16x2.f32 %0, %1, %2;" : "=r"(r) : "f"(hi), "f"(lo));
    return r;
}

__global__ void conv_f16(const float4* __restrict__ src, __half2* __restrict__ dst, int n4) {
    int i = blockIdx.x * 256 + threadIdx.x;
    if (i >= n4) return;
    float4 v = src[i];
    dst[2 * i]     = __floats2half2_rn(v.x, v.y);
    dst[2 * i + 1] = __floats2half2_rn(v.z, v.w);
}

__global__ void lam_kernel(const float* __restrict__ Wl1, const float* __restrict__ bl1,
                           const float* __restrict__ Wl2, const float* __restrict__ bl2) {
    int t = blockIdx.x * blockDim.x + threadIdx.x;
    if (t >= SEQ) return;
    float lp = logf((float)t + 1.0f);
    float h1[64];
#pragma unroll
    for (int u = 0; u < 64; u++) {
        float v = lp * Wl1[u] + bl1[u];
        h1[u] = v > 0.0f ? v : 0.0f;
    }
#pragma unroll
    for (int h = 0; h < HEADS; h++) {
        float s = bl2[h];
#pragma unroll
        for (int u = 0; u < 64; u++) s += h1[u] * Wl2[h * 64 + u];
        g_lam[h * SEQ + t] = 1.0f / (1.0f + expf(-s));
    }
}

// ---------------------------------------------------------------------------
// FP16 mma.sync GEMM with ldmatrix fragment loads.
// ---------------------------------------------------------------------------
#define GBM 128
#define GBN 128
#define GBK 32
#define HSTRIDE 40                        // halfs per row (80 bytes)
#define OPER_HB (128 * HSTRIDE * 2)
#define STAGE_B (2 * OPER_HB)
#define NSTAGE 3
#define GEMM_SMEM (NSTAGE * STAGE_B)
#define NKIT (CDIM / GBK)

__device__ __forceinline__ void mma_f16(float* c, const uint32_t* a,
                                        uint32_t b0, uint32_t b1) {
    asm volatile(
        "mma.sync.aligned.m16n8k16.row.col.f32.f16.f16.f32 "
        "{%0,%1,%2,%3}, {%4,%5,%6,%7}, {%8,%9}, {%0,%1,%2,%3};"
        : "+f"(c[0]), "+f"(c[1]), "+f"(c[2]), "+f"(c[3])
        : "r"(a[0]), "r"(a[1]), "r"(a[2]), "r"(a[3]), "r"(b0), "r"(b1));
}

__device__ __forceinline__ void ld_gemm16(char* st, const __half* __restrict__ A,
                                          const __half* __restrict__ B,
                                          int bm, int bn, int k0, int tid) {
#pragma unroll
    for (int i = 0; i < 2; i++) {
        int idx = tid + i * 256;
        int row = idx >> 2;
        int c4  = idx & 3;
        __pipeline_memcpy_async(st + (row * HSTRIDE + c4 * 8) * 2,
                                A + (size_t)(bm + row) * CDIM + k0 + c4 * 8, 16);
        __pipeline_memcpy_async(st + OPER_HB + (row * HSTRIDE + c4 * 8) * 2,
                                B + (size_t)(bn + row) * CDIM + k0 + c4 * 8, 16);
    }
}

__global__ __launch_bounds__(256, 2) void gemm_f16(const __half* __restrict__ A,
                                                   const __half* __restrict__ B,
                                                   const float* __restrict__ bias,
                                                   float* __restrict__ Y, int mode) {
    extern __shared__ char smc[];
    const int tid = threadIdx.x;
    const int w = tid >> 5, lane = tid & 31;
    const int g = lane >> 2, tg = lane & 3;
    const int mo = (w >> 2) * 64;
    const int no = (w & 3) * 32;
    const int bm = blockIdx.y * GBM;
    const int bn = blockIdx.x * GBN;

    // ldmatrix per-lane addressing
    const int aRow = lane & 15;                       // A: rows 0-15 pattern
    const int aCol = ((lane >> 4) & 1) * 16;          // A: 16B col half
    const int bRow = (lane & 7) + ((lane & 16) ? 8 : 0);  // B: row octet select
    const int bCol = (lane & 8) ? 16 : 0;             // B: 16B col half

    const uint32_t sbu = smem_u32(smc);

    float acc[4][4][4];
#pragma unroll
    for (int mi = 0; mi < 4; mi++)
#pragma unroll
        for (int ni = 0; ni < 4; ni++)
#pragma unroll
            for (int e = 0; e < 4; e++) acc[mi][ni][e] = 0.0f;

    ld_gemm16(smc, A, B, bm, bn, 0, tid);
    __pipeline_commit();
    ld_gemm16(smc + STAGE_B, A, B, bm, bn, GBK, tid);
    __pipeline_commit();

    int buf_next = 2;
    for (int it = 0; it < NKIT; it++) {
        if (it + 2 < NKIT) {
            ld_gemm16(smc + buf_next * STAGE_B, A, B, bm, bn, (it + 2) * GBK, tid);
            __pipeline_commit();
            __pipeline_wait_prior(2);
            buf_next = (buf_next + 1) % NSTAGE;
        } else if (it + 1 < NKIT) {
            __pipeline_wait_prior(1);
        } else {
            __pipeline_wait_prior(0);
        }
        __syncthreads();

        const uint32_t sAu = sbu + (it % NSTAGE) * STAGE_B;
        const uint32_t sBu = sAu + OPER_HB;

#pragma unroll
        for (int ks = 0; ks < 2; ks++) {
            uint32_t bfr[4][2];
#pragma unroll
            for (int nip = 0; nip < 2; nip++) {
                uint32_t r0, r1, r2, r3;
                ldm_x4(r0, r1, r2, r3,
                       sBu + (uint32_t)(no + nip * 16 + bRow) * 80 + ks * 32 + bCol);
                bfr[nip * 2 + 0][0] = r0; bfr[nip * 2 + 0][1] = r1;
                bfr[nip * 2 + 1][0] = r2; bfr[nip * 2 + 1][1] = r3;
            }
#pragma unroll
            for (int mi = 0; mi < 4; mi++) {
                uint32_t afr[4];
                ldm_x4(afr[0], afr[1], afr[2], afr[3],
                       sAu + (uint32_t)(mo + mi * 16 + aRow) * 80 + ks * 32 + aCol);
#pragma unroll
                for (int ni = 0; ni < 4; ni++)
                    mma_f16(acc[mi][ni], afr, bfr[ni][0], bfr[ni][1]);
            }
        }
        __syncthreads();
    }

    // epilogue
#pragma unroll
    for (int mi = 0; mi < 4; mi++) {
        const int m0 = bm + mo + mi * 16 + g;
#pragma unroll
        for (int ni = 0; ni < 4; ni++) {
            const int n = bn + no + ni * 8 + tg * 2;
            const float* c = acc[mi][ni];
            if (mode == 0) {
                const int which = n >> 10;
                const int cr = n & 1023;
                const int h = cr >> 6, d = cr & 63;
#pragma unroll
                for (int rr = 0; rr < 2; rr++) {
                    const int m = m0 + rr * 8;
                    const int b = m >> 12, t = m & 4095;
                    float v0 = c[rr * 2], v1 = c[rr * 2 + 1];
                    if (which == 0) { v0 *= 0.125f; v1 *= 0.125f; }
                    __nv_bfloat16 h0 = __float2bfloat16(v0);
                    __nv_bfloat16 h1 = __float2bfloat16(v1);
                    __nv_bfloat16 l0 = __float2bfloat16(v0 - __bfloat162float(h0));
                    __nv_bfloat16 l1 = __float2bfloat16(v1 - __bfloat162float(h1));
                    if (which < 2) {
                        const size_t off = ((size_t)(b * HEADS + h) * SEQ + t) * DH + d;
                        __nv_bfloat162 ph, pl;
                        ph.x = h0; ph.y = h1; pl.x = l0; pl.y = l1;
                        if (which == 0) {
                            *(__nv_bfloat162*)(g_qh + off) = ph;
                            *(__nv_bfloat162*)(g_ql + off) = pl;
                        } else {
                            *(__nv_bfloat162*)(g_kh + off) = ph;
                            *(__nv_bfloat162*)(g_kl + off) = pl;
                        }
                    } else {
                        const size_t off = ((size_t)(b * HEADS + h) * DH + d) * SEQ + t;
                        g_vth[off] = h0;       g_vth[off + SEQ] = h1;
                        g_vtl[off] = l0;       g_vtl[off + SEQ] = l1;
                    }
                }
            } else {
                const float2 bv = *(const float2*)(bias + n);
#pragma unroll
                for (int rr = 0; rr < 2; rr++) {
                    const int m = m0 + rr * 8;
                    *(float2*)(Y + (size_t)m * CDIM + n) =
                        make_float2(c[rr * 2] + bv.x, c[rr * 2 + 1] + bv.y);
                }
            }
        }
    }
}

// ---------------------------------------------------------------------------
// Stage 3: attention, bf16 hi/lo split mma with ldmatrix loads.
// ---------------------------------------------------------------------------
#define AQS 72     // K/Q row stride in halfs (144 bytes)
#define AVS 136    // Vt row stride in halfs (272 bytes)
#define ATT_SMEM (2*(128*AQS*2) + 2*(128*AQS*2) + 2*(64*AVS*2) + 512*4)

__device__ __forceinline__ void mma_bf16(float* c, const uint32_t* a,
                                         uint32_t b0, uint32_t b1) {
    asm volatile(
        "mma.sync.aligned.m16n8k16.row.col.f32.bf16.bf16.f32 "
        "{%0,%1,%2,%3}, {%4,%5,%6,%7}, {%8,%9}, {%0,%1,%2,%3};"
        : "+f"(c[0]), "+f"(c[1]), "+f"(c[2]), "+f"(c[3])
        : "r"(a[0]), "r"(a[1]), "r"(a[2]), "r"(a[3]), "r"(b0), "r"(b1));
}

__global__ __launch_bounds__(256, 2) void attn_mma() {
    extern __shared__ char smb[];
    __nv_bfloat16* sQh = (__nv_bfloat16*)smb;
    __nv_bfloat16* sQl = sQh + 128 * AQS;
    __nv_bfloat16* sKh = sQl + 128 * AQS;
    __nv_bfloat16* sKl = sKh + 128 * AQS;
    __nv_bfloat16* sVh = sKl + 128 * AQS;
    __nv_bfloat16* sVl = sVh + 64 * AVS;
    float* slam = (float*)(sVl + 64 * AVS);

    const int bx = blockIdx.x;
    const int qt = bx & 3;
    const int chunk = (bx >> 2) & 7;
    const int h = (bx >> 5) & 15;
    const int b = bx >> 9;
    const int tid = threadIdx.x;
    const int w = tid >> 5, lane = tid & 31;
    const int g = lane >> 2, tg = lane & 3;
    const int rw = w * 16;

    const int aRow = lane & 15;
    const int aCol = ((lane >> 4) & 1) * 16;
    const int bRow = (lane & 7) + ((lane & 16) ? 8 : 0);
    const int bCol = (lane & 8) ? 16 : 0;

    const uint32_t uQh = smem_u32(sQh), uQl = smem_u32(sQl);
    const uint32_t uKh = smem_u32(sKh), uKl = smem_u32(sKl);
    const uint32_t uVh = smem_u32(sVh), uVl = smem_u32(sVl);

    const size_t head = (size_t)(b * HEADS + h);
    const size_t qoff = (head * SEQ + chunk * CS + qt * QT) * DH;
    const size_t kbase_g = (head * SEQ + chunk * CS) * DH;
    const size_t vbase_g = head * DH * SEQ + (size_t)chunk * CS;

    for (int j = tid; j < CS; j += 256) slam[j] = g_lam[h * SEQ + chunk * CS + j];
#pragma unroll
    for (int i = 0; i < 4; i++) {
        int idx = tid + i * 256;
        int r = idx >> 3, c = idx & 7;
        __pipeline_memcpy_async(sQh + r * AQS + c * 8, g_qh + qoff + r * 64 + c * 8, 16);
        __pipeline_memcpy_async(sQl + r * AQS + c * 8, g_ql + qoff + r * 64 + c * 8, 16);
    }
    __pipeline_commit();

    float oacc[8][4];
#pragma unroll
    for (int d = 0; d < 8; d++)
#pragma unroll
        for (int e = 0; e < 4; e++) oacc[d][e] = 0.0f;
    float m0 = -1e30f, m1 = -1e30f, l0 = 0.0f, l1 = 0.0f;

    for (int kt = 0; kt < 4; kt++) {
        __syncthreads();
#pragma unroll
        for (int i = 0; i < 4; i++) {
            int idx = tid + i * 256;
            int r = idx >> 3, c = idx & 7;
            size_t src = kbase_g + (size_t)(kt * 128 + r) * 64 + c * 8;
            __pipeline_memcpy_async(sKh + r * AQS + c * 8, g_kh + src, 16);
            __pipeline_memcpy_async(sKl + r * AQS + c * 8, g_kl + src, 16);
        }
#pragma unroll
        for (int i = 0; i < 4; i++) {
            int idx = tid + i * 256;
            int r = idx >> 4, c = idx & 15;
            size_t src = vbase_g + (size_t)r * SEQ + kt * 128 + c * 8;
            __pipeline_memcpy_async(sVh + r * AVS + c * 8, g_vth + src, 16);
            __pipeline_memcpy_async(sVl + r * AVS + c * 8, g_vtl + src, 16);
        }
        __pipeline_commit();
        __pipeline_wait_prior(0);
        __syncthreads();

#pragma unroll
        for (int hh = 0; hh < 2; hh++) {
            const int kb = hh * 64;

            // ---- S = Q K^T ----
            float sacc[8][4];
#pragma unroll
            for (int j = 0; j < 8; j++)
#pragma unroll
                for (int e = 0; e < 4; e++) sacc[j][e] = 0.0f;

#pragma unroll
            for (int ks = 0; ks < 4; ks++) {
                uint32_t ah[4], al[4];
                ldm_x4(ah[0], ah[1], ah[2], ah[3],
                       uQh + (uint32_t)(rw + aRow) * 144 + ks * 32 + aCol);
                ldm_x4(al[0], al[1], al[2], al[3],
                       uQl + (uint32_t)(rw + aRow) * 144 + ks * 32 + aCol);
#pragma unroll
                for (int jp = 0; jp < 4; jp++) {
                    uint32_t kh0, kh1, kh2, kh3, kl0, kl1, kl2, kl3;
                    const uint32_t koff = (uint32_t)(kb + jp * 16 + bRow) * 144 + ks * 32 + bCol;
                    ldm_x4(kh0, kh1, kh2, kh3, uKh + koff);
                    ldm_x4(kl0, kl1, kl2, kl3, uKl + koff);
                    mma_bf16(sacc[2 * jp], ah, kh0, kh1);
                    mma_bf16(sacc[2 * jp], ah, kl0, kl1);
                    mma_bf16(sacc[2 * jp], al, kh0, kh1);
                    mma_bf16(sacc[2 * jp + 1], ah, kh2, kh3);
                    mma_bf16(sacc[2 * jp + 1], ah, kl2, kl3);
                    mma_bf16(sacc[2 * jp + 1], al, kh2, kh3);
                }
            }

            // ---- gate + online softmax ----
            float ml0 = -1e30f, ml1 = -1e30f;
#pragma unroll
            for (int j = 0; j < 8; j++) {
                float2 la = *(float2*)&slam[kt * 128 + kb + j * 8 + 2 * tg];
                sacc[j][0] *= la.x; sacc[j][1] *= la.y;
                sacc[j][2] *= la.x; sacc[j][3] *= la.y;
                ml0 = fmaxf(ml0, fmaxf(sacc[j][0], sacc[j][1]));
                ml1 = fmaxf(ml1, fmaxf(sacc[j][2], sacc[j][3]));
            }
#pragma unroll
            for (int s = 1; s < 4; s <<= 1) {
                ml0 = fmaxf(ml0, __shfl_xor_sync(0xffffffffu, ml0, s));
                ml1 = fmaxf(ml1, __shfl_xor_sync(0xffffffffu, ml1, s));
            }
            const float mn0 = fmaxf(m0, ml0);
            const float mn1 = fmaxf(m1, ml1);
            const float cr0 = __expf(m0 - mn0);
            const float cr1 = __expf(m1 - mn1);
            float rs0 = 0.0f, rs1 = 0.0f;
#pragma unroll
            for (int j = 0; j < 8; j++) {
                sacc[j][0] = __expf(sacc[j][0] - mn0);
                sacc[j][1] = __expf(sacc[j][1] - mn0);
                sacc[j][2] = __expf(sacc[j][2] - mn1);
                sacc[j][3] = __expf(sacc[j][3] - mn1);
                rs0 += sacc[j][0] + sacc[j][1];
                rs1 += sacc[j][2] + sacc[j][3];
            }
#pragma unroll
            for (int s = 1; s < 4; s <<= 1) {
                rs0 += __shfl_xor_sync(0xffffffffu, rs0, s);
                rs1 += __shfl_xor_sync(0xffffffffu, rs1, s);
            }
            l0 = l0 * cr0 + rs0;  m0 = mn0;
            l1 = l1 * cr1 + rs1;  m1 = mn1;
#pragma unroll
            for (int d = 0; d < 8; d++) {
                oacc[d][0] *= cr0; oacc[d][1] *= cr0;
                oacc[d][2] *= cr1; oacc[d][3] *= cr1;
            }

            // ---- O += P V ----
#pragma unroll
            for (int kp = 0; kp < 4; kp++) {
                uint32_t ph[4], pl[4];
#pragma unroll
                for (int u = 0; u < 2; u++) {
                    const float* p = sacc[2 * kp + u];
                    float h0f = __bfloat162float(__float2bfloat16(p[0]));
                    float h1f = __bfloat162float(__float2bfloat16(p[1]));
                    float h2f = __bfloat162float(__float2bfloat16(p[2]));
                    float h3f = __bfloat162float(__float2bfloat16(p[3]));
                    ph[0 + 2 * u] = pk2bf(h0f, h1f);
                    ph[1 + 2 * u] = pk2bf(h2f, h3f);
                    pl[0 + 2 * u] = pk2bf(p[0] - h0f, p[1] - h1f);
                    pl[1 + 2 * u] = pk2bf(p[2] - h2f, p[3] - h3f);
                }
#pragma unroll
                for (int dp = 0; dp < 4; dp++) {
                    uint32_t vh0, vh1, vh2, vh3, vl0, vl1, vl2, vl3;
                    const uint32_t voff = (uint32_t)(dp * 16 + bRow) * 272 +
                                          (uint32_t)(kb + kp * 16) * 2 + bCol;
                    ldm_x4(vh0, vh1, vh2, vh3, uVh + voff);
                    ldm_x4(vl0, vl1, vl2, vl3, uVl + voff);
                    mma_bf16(oacc[2 * dp], ph, vh0, vh1);
                    mma_bf16(oacc[2 * dp], ph, vl0, vl1);
                    mma_bf16(oacc[2 * dp], pl, vh0, vh1);
                    mma_bf16(oacc[2 * dp + 1], ph, vh2, vh3);
                    mma_bf16(oacc[2 * dp + 1], ph, vl2, vl3);
                    mma_bf16(oacc[2 * dp + 1], pl, vh2, vh3);
                }
            }
        }
    }

    // epilogue: normalize, write fp16
    const float inv0 = 1.0f / l0, inv1 = 1.0f / l1;
    const int t0 = chunk * CS + qt * QT + rw;
    const size_t row0 = ((size_t)b * SEQ + t0 + g) * CDIM + h * DH;
    const size_t row1 = row0 + (size_t)8 * CDIM;
#pragma unroll
    for (int d = 0; d < 8; d++) {
        *(__half2*)(g_a16 + row0 + d * 8 + 2 * tg) =
            __floats2half2_rn(oacc[d][0] * inv0, oacc[d][1] * inv0);
        *(__half2*)(g_a16 + row1 + d * 8 + 2 * tg) =
            __floats2half2_rn(oacc[d][2] * inv1, oacc[d][3] * inv1);
    }
}

// ---------------------------------------------------------------------------
extern "C" void kernel_launch(void* const* d_in, const int* in_sizes, int n_in,
                              void* d_out, int out_size) {
    const float* x    = (const float*)d_in[0];
    const float* Wqkv = (const float*)d_in[1];
    const float* Wout = (const float*)d_in[2];
    const float* bout = (const float*)d_in[3];
    const float* Wl1  = (const float*)d_in[4];
    const float* bl1  = (const float*)d_in[5];
    const float* Wl2  = (const float*)d_in[6];
    const float* bl2  = (const float*)d_in[7];
    float* out = (float*)d_out;

    cudaFuncSetAttribute(attn_mma, cudaFuncAttributeMaxDynamicSharedMemorySize, ATT_SMEM);
    cudaFuncSetAttribute(gemm_f16, cudaFuncAttributeMaxDynamicSharedMemorySize, GEMM_SMEM);

    __half *x16, *w16, *wo16, *a16;
    cudaGetSymbolAddress((void**)&x16, g_x16);
    cudaGetSymbolAddress((void**)&w16, g_w16);
    cudaGetSymbolAddress((void**)&wo16, g_wo16);
    cudaGetSymbolAddress((void**)&a16, g_a16);

    lam_kernel<<<SEQ / 256, 256>>>(Wl1, bl1, Wl2, bl2);

    {
        int n4 = M_TOT * CDIM / 4;
        conv_f16<<<(n4 + 255) / 256, 256>>>((const float4*)x, (__half2*)x16, n4);
        n4 = 3 * CDIM * CDIM / 4;
        conv_f16<<<(n4 + 255) / 256, 256>>>((const float4*)Wqkv, (__half2*)w16, n4);
        n4 = CDIM * CDIM / 4;
        conv_f16<<<(n4 + 255) / 256, 256>>>((const float4*)Wout, (__half2*)wo16, n4);
    }

    gemm_f16<<<dim3(3 * CDIM / GBN, M_TOT / GBM), 256, GEMM_SMEM>>>(
        x16, w16, nullptr, nullptr, 0);

    attn_mma<<<BATCH * HEADS * 8 * (CS / QT), 256, ATT_SMEM>>>();

    gemm_f16<<<dim3(CDIM / GBN, M_TOT / GBM), 256, GEMM_SMEM>>>(
        a16, wo16, bout, out, 1);
}